// round 8
// baseline (speedup 1.0000x reference)
#include <cuda_runtime.h>
#include <cuda_fp16.h>
#include <cstdint>

#define N_NODES 100000
#define N_EDGES 1600000
#define N_TOT   1700000           // edges + self loops
#define NEG_SLOPE 0.2f
#define EPS 1e-16f
#define SCAN_B 1024
#define NSCAN ((N_NODES + SCAN_B - 1) / SCAN_B)   // 98

// ---------------- scratch (device globals; no allocation allowed) ----------
__device__ __half2 g_h1h[N_NODES * 32];  // layer-1 features (fp16, gather-only)
__device__ float g_h2[N_NODES * 8];      // layer-2 features (padded 7->8)
__device__ float g_as[N_NODES];          // layer-1 alpha_src per node
__device__ float g_ad[N_NODES];          // layer-1 alpha_dst per node
__device__ float g_as2[N_NODES];         // layer-2 alpha_src per node
__device__ float g_ad2[N_NODES];         // layer-2 alpha_dst per node
__device__ int   g_deg[N_NODES];         // in-degree histogram (zeroed by scan)
__device__ int   g_off[N_NODES + 1];     // CSR row offsets (by dst)
__device__ int   g_cur[N_NODES];         // scatter cursors
__device__ int   g_bsum[NSCAN];          // scan block sums
__device__ int   g_arrive;               // grid-barrier counters (self-reset)
__device__ int   g_depart;
__device__ int2  g_es[N_TOT];            // CSR payload: (src, adj bits)

// ---------------- tf32 helpers ---------------------------------------------
__device__ __forceinline__ uint32_t f2tf32(float f) {
    uint32_t r;
    asm("cvt.rna.tf32.f32 %0, %1;" : "=r"(r) : "f"(f));
    return r;
}

__device__ __forceinline__ void mma16n8k8(float* d,
                                          uint32_t a0, uint32_t a1,
                                          uint32_t a2, uint32_t a3,
                                          uint32_t b0, uint32_t b1) {
    asm volatile(
        "mma.sync.aligned.m16n8k8.row.col.f32.tf32.tf32.f32 "
        "{%0,%1,%2,%3}, {%4,%5,%6,%7}, {%8,%9}, {%0,%1,%2,%3};"
        : "+f"(d[0]), "+f"(d[1]), "+f"(d[2]), "+f"(d[3])
        : "r"(a0), "r"(a1), "r"(a2), "r"(a3), "r"(b0), "r"(b1));
}

// ---------------- K1: h1 = x @ W1 via 3xTF32 mma, fused alphas -------------
// B (W1) is pre-split into packed (hi,lo) tf32 pairs at staging time, so the
// mainloop does zero B conversions (was the ALU-pipe bottleneck).
__global__ __launch_bounds__(256, 1)
void gemm1_mma_kernel(const float* __restrict__ x,
                      const float* __restrict__ W1,
                      const float* __restrict__ a_src,
                      const float* __restrict__ a_dst) {
    extern __shared__ char smem_raw[];
    float* As  = (float*)smem_raw;                 // 128x128 fp32, XOR-swizzled
    uint2* Bsp = (uint2*)(smem_raw + 128 * 128 * 4); // 128x64 (hi,lo), swizzled
    __shared__ float as_s[64], ad_s[64];

    const int t = threadIdx.x;
    const int rbase = blockIdx.x * 128;

#pragma unroll
    for (int i = 0; i < 16; ++i) {
        int fid = i * 256 + t;
        int row = fid >> 5;
        int k4  = (fid & 31) * 4;
        int gr  = rbase + row;
        float4 v = make_float4(0.f, 0.f, 0.f, 0.f);
        if (gr < N_NODES) v = *(const float4*)&x[gr * 128 + k4];
        int ks = k4 ^ ((row & 7) << 2);
        *(float4*)&As[row * 128 + ks] = v;
    }
#pragma unroll
    for (int i = 0; i < 8; ++i) {
        int fid = i * 256 + t;
        int k  = fid >> 4;
        int n4 = (fid & 15) * 4;
        float4 v = *(const float4*)&W1[k * 64 + n4];
        int ns = n4 ^ ((k & 3) << 3);
        uint2* dst = &Bsp[k * 64 + ns];
        float vv[4] = {v.x, v.y, v.z, v.w};
#pragma unroll
        for (int jj = 0; jj < 4; ++jj) {
            uint32_t hi = f2tf32(vv[jj]);
            uint32_t lo = f2tf32(vv[jj] - __uint_as_float(hi));
            dst[jj] = make_uint2(hi, lo);
        }
    }
    if (t < 64)       as_s[t]      = a_src[t];
    else if (t < 128) ad_s[t - 64] = a_dst[t - 64];
    __syncthreads();

    const int w    = t >> 5;
    const int lane = t & 31;
    const int g    = lane >> 2;
    const int tg   = lane & 3;
    const int wr   = w * 16;

    float acc[8][4];
#pragma unroll
    for (int i = 0; i < 8; ++i)
#pragma unroll
        for (int j = 0; j < 4; ++j) acc[i][j] = 0.f;

    const int aOff0 = (wr + g) * 128;
    const int aOff1 = aOff0 + 8 * 128;
    const int sA    = g << 2;

#pragma unroll
    for (int step = 0; step < 16; ++step) {
        const int kb  = step * 8;
        const int ia0 = (kb + tg) ^ sA;
        float af0 = As[aOff0 + ia0];
        float af1 = As[aOff1 + ia0];
        float af2 = As[aOff0 + (ia0 ^ 4)];
        float af3 = As[aOff1 + (ia0 ^ 4)];
        uint32_t ah0 = f2tf32(af0), ah1 = f2tf32(af1);
        uint32_t ah2 = f2tf32(af2), ah3 = f2tf32(af3);
        uint32_t al0 = f2tf32(af0 - __uint_as_float(ah0));
        uint32_t al1 = f2tf32(af1 - __uint_as_float(ah1));
        uint32_t al2 = f2tf32(af2 - __uint_as_float(ah2));
        uint32_t al3 = f2tf32(af3 - __uint_as_float(ah3));
        const int bRow = (kb + tg) * 64 + g;
#pragma unroll
        for (int nt = 0; nt < 8; ++nt) {
            int bi0 = bRow + ((nt ^ tg) << 3);
            uint2 b0 = Bsp[bi0];          // k = kb+tg
            uint2 b1 = Bsp[bi0 + 256];    // k = kb+tg+4
            mma16n8k8(acc[nt], ah0, ah1, ah2, ah3, b0.x, b1.x);  // hiA*hiB
            mma16n8k8(acc[nt], al0, al1, al2, al3, b0.x, b1.x);  // loA*hiB
            mma16n8k8(acc[nt], ah0, ah1, ah2, ah3, b0.y, b1.y);  // hiA*loB
        }
    }

    const int r0 = rbase + wr + g;
    const int r1 = r0 + 8;
    float pas0 = 0.f, pad0 = 0.f, pas1 = 0.f, pad1 = 0.f;
#pragma unroll
    for (int nt = 0; nt < 8; ++nt) {
        int c = nt * 8 + 2 * tg;
        float2 av = *(const float2*)&as_s[c];
        float2 dv = *(const float2*)&ad_s[c];
        pas0 += acc[nt][0] * av.x + acc[nt][1] * av.y;
        pad0 += acc[nt][0] * dv.x + acc[nt][1] * dv.y;
        pas1 += acc[nt][2] * av.x + acc[nt][3] * av.y;
        pad1 += acc[nt][2] * dv.x + acc[nt][3] * dv.y;
        if (r0 < N_NODES)
            g_h1h[r0 * 32 + nt * 4 + tg] = __floats2half2_rn(acc[nt][0], acc[nt][1]);
        if (r1 < N_NODES)
            g_h1h[r1 * 32 + nt * 4 + tg] = __floats2half2_rn(acc[nt][2], acc[nt][3]);
    }
#pragma unroll
    for (int off = 1; off <= 2; off <<= 1) {
        pas0 += __shfl_xor_sync(0xffffffffu, pas0, off);
        pad0 += __shfl_xor_sync(0xffffffffu, pad0, off);
        pas1 += __shfl_xor_sync(0xffffffffu, pas1, off);
        pad1 += __shfl_xor_sync(0xffffffffu, pad1, off);
    }
    if (tg == 0) {
        if (r0 < N_NODES) { g_as[r0] = pas0; g_ad[r0] = pad0; }
        if (r1 < N_NODES) { g_as[r1] = pas1; g_ad[r1] = pad1; }
    }
}

// ---------------- CSR build (side stream, overlapped with gemm1) -----------
__global__ void hist_kernel(const int* __restrict__ ei) {
    int t = blockIdx.x * blockDim.x + threadIdx.x;
    int e4 = t * 4;
    if (e4 + 3 < N_EDGES) {
        int4 d4 = *(const int4*)&ei[N_EDGES + e4];
        atomicAdd(&g_deg[d4.x], 1);
        atomicAdd(&g_deg[d4.y], 1);
        atomicAdd(&g_deg[d4.z], 1);
        atomicAdd(&g_deg[d4.w], 1);
    } else {
        for (int e = e4; e < N_EDGES && e < e4 + 4; ++e)
            atomicAdd(&g_deg[ei[N_EDGES + e]], 1);
    }
    if (t < N_NODES) atomicAdd(&g_deg[t], 1);
}

// Fused scan: block-local scan + grid barrier + global prefix + cursor init
// + g_deg zeroing. 98 blocks, all resident -> spin barrier is safe.
__global__ void fused_scan_kernel() {
    __shared__ int sh[256];
    __shared__ int bs[NSCAN];
    const int tid = threadIdx.x;
    const int b   = blockIdx.x;
    const int base = b * SCAN_B + tid * 4;

    int v[4];
#pragma unroll
    for (int k = 0; k < 4; ++k)
        v[k] = (base + k < N_NODES) ? g_deg[base + k] : 0;
    int local = v[0] + v[1] + v[2] + v[3];
    sh[tid] = local;
    __syncthreads();
    for (int off = 1; off < 256; off <<= 1) {
        int t2 = (tid >= off) ? sh[tid - off] : 0;
        __syncthreads();
        sh[tid] += t2;
        __syncthreads();
    }
    int incl = sh[tid];

    if (tid == 0) {
        g_bsum[b] = sh[255];
        __threadfence();
        atomicAdd(&g_arrive, 1);
        while (*(volatile int*)&g_arrive < NSCAN) { }
    }
    __syncthreads();

    if (tid < NSCAN) bs[tid] = *(volatile int*)&g_bsum[tid];
    __syncthreads();
    int bpre = 0;
    for (int i = 0; i < b; ++i) bpre += bs[i];

    int run = bpre + incl - local;
#pragma unroll
    for (int k = 0; k < 4; ++k) {
        if (base + k < N_NODES) {
            g_off[base + k] = run;
            g_cur[base + k] = run;
            g_deg[base + k] = 0;
        }
        run += v[k];
    }
    if (b == NSCAN - 1 && tid == 255) g_off[N_NODES] = N_TOT;

    __syncthreads();
    if (tid == 0) {
        int old = atomicAdd(&g_depart, 1);
        if (old == NSCAN - 1) { g_depart = 0; g_arrive = 0; }
    }
}

__global__ void scatter_kernel(const int* __restrict__ ei,
                               const float* __restrict__ ew) {
    int e = blockIdx.x * blockDim.x + threadIdx.x;
    if (e >= N_TOT) return;
    int s, d; float adj;
    if (e < N_EDGES) {
        s = ei[e]; d = ei[N_EDGES + e];
        adj = 1.f - 1.f / ew[e];
    } else {
        s = d = e - N_EDGES;
        adj = 0.f;
    }
    int pos = atomicAdd(&g_cur[d], 1);
    g_es[pos] = make_int2(s, __float_as_int(adj));
}

// ---------------- K2: fused layer-1 softmax+aggregate + layer-2 features ----
__global__ void agg1_csr_kernel(const float* __restrict__ b1,
                                const float* __restrict__ W2,
                                const float* __restrict__ a_src2,
                                const float* __restrict__ a_dst2) {
    __shared__ float w2s[448];
    __shared__ float as2s[8], ad2s[8];
    __shared__ float b1s[64];
    int tid = threadIdx.x;
    if (tid < 224) { w2s[tid] = W2[tid]; w2s[tid + 224] = W2[tid + 224]; }
    if (tid < 7)   { as2s[tid] = a_src2[tid]; ad2s[tid] = a_dst2[tid]; }
    if (tid < 64)  b1s[tid] = b1[tid];
    __syncthreads();

    int d    = (blockIdx.x * blockDim.x + tid) >> 5;
    int lane = tid & 31;
    if (d >= N_NODES) return;

    float ad_d = g_ad[d];
    int j = g_off[d], end = g_off[d + 1];
    float den = 0.f, a0 = 0.f, a1 = 0.f;

    for (; j + 7 < end; j += 8) {
        int2 e[8];
#pragma unroll
        for (int q = 0; q < 8; ++q) e[q] = g_es[j + q];
        float sa[8]; __half2 hh[8];
#pragma unroll
        for (int q = 0; q < 8; ++q) {
            sa[q] = g_as[e[q].x];
            hh[q] = g_h1h[e[q].x * 32 + lane];
        }
#pragma unroll
        for (int q = 0; q < 8; ++q) {
            float xx = sa[q] + ad_d; xx = (xx > 0.f) ? xx : NEG_SLOPE * xx;
            float ea = __expf(xx + __int_as_float(e[q].y));
            float2 f = __half22float2(hh[q]);
            den += ea; a0 += ea * f.x; a1 += ea * f.y;
        }
    }
    if (j + 3 < end) {
        int2 e[4];
#pragma unroll
        for (int q = 0; q < 4; ++q) e[q] = g_es[j + q];
        float sa[4]; __half2 hh[4];
#pragma unroll
        for (int q = 0; q < 4; ++q) {
            sa[q] = g_as[e[q].x];
            hh[q] = g_h1h[e[q].x * 32 + lane];
        }
#pragma unroll
        for (int q = 0; q < 4; ++q) {
            float xx = sa[q] + ad_d; xx = (xx > 0.f) ? xx : NEG_SLOPE * xx;
            float ea = __expf(xx + __int_as_float(e[q].y));
            float2 f = __half22float2(hh[q]);
            den += ea; a0 += ea * f.x; a1 += ea * f.y;
        }
        j += 4;
    }
    for (; j < end; ++j) {
        int2 e0 = g_es[j];
        float sa0 = g_as[e0.x];
        __half2 h0 = g_h1h[e0.x * 32 + lane];
        float xx = sa0 + ad_d; xx = (xx > 0.f) ? xx : NEG_SLOPE * xx;
        float ea = __expf(xx + __int_as_float(e0.y));
        float2 f = __half22float2(h0);
        den += ea; a0 += ea * f.x; a1 += ea * f.y;
    }

    float inv = 1.f / (den + EPS);
    float f0 = fmaxf(fmaf(a0, inv, b1s[lane * 2]),     0.f);
    float f1 = fmaxf(fmaf(a1, inv, b1s[lane * 2 + 1]), 0.f);

    float p[7];
#pragma unroll
    for (int c = 0; c < 7; ++c)
        p[c] = f0 * w2s[(lane * 2) * 7 + c] + f1 * w2s[(lane * 2 + 1) * 7 + c];
#pragma unroll
    for (int off = 16; off > 0; off >>= 1)
#pragma unroll
        for (int c = 0; c < 7; ++c)
            p[c] += __shfl_xor_sync(0xffffffffu, p[c], off);

    if (lane == 0) {
        float4 v0 = make_float4(p[0], p[1], p[2], p[3]);
        float4 v1 = make_float4(p[4], p[5], p[6], 0.f);
        *(float4*)&g_h2[d * 8]     = v0;
        *(float4*)&g_h2[d * 8 + 4] = v1;
        float s2 = 0.f, t2 = 0.f;
#pragma unroll
        for (int c = 0; c < 7; ++c) {
            s2 += p[c] * as2s[c];
            t2 += p[c] * ad2s[c];
        }
        g_as2[d] = s2;
        g_ad2[d] = t2;
    }
}

// ---------------- K3: fused layer-2 softmax+aggregate (8 lanes / dst) -------
__global__ void agg2_csr_kernel(float* __restrict__ out,
                                const float* __restrict__ b2) {
    int gt = blockIdx.x * blockDim.x + threadIdx.x;
    int d  = gt >> 3;
    int c  = gt & 7;
    if (d >= N_NODES) return;

    float ad_d = g_ad2[d];
    int j = g_off[d], end = g_off[d + 1];
    float den = 0.f, acc = 0.f;
    for (; j + 3 < end; j += 4) {
        int2 e[4];
#pragma unroll
        for (int q = 0; q < 4; ++q) e[q] = g_es[j + q];
        float sa[4], hv[4];
#pragma unroll
        for (int q = 0; q < 4; ++q) {
            sa[q] = g_as2[e[q].x];
            hv[q] = g_h2[e[q].x * 8 + c];
        }
#pragma unroll
        for (int q = 0; q < 4; ++q) {
            float a = sa[q] + ad_d; a = (a > 0.f) ? a : NEG_SLOPE * a;
            float ea = __expf(a + __int_as_float(e[q].y));
            den += ea; acc += ea * hv[q];
        }
    }
    for (; j < end; ++j) {
        int2 e0 = g_es[j];
        float a = g_as2[e0.x] + ad_d; a = (a > 0.f) ? a : NEG_SLOPE * a;
        float ea = __expf(a + __int_as_float(e0.y));
        den += ea;
        acc += ea * g_h2[e0.x * 8 + c];
    }
    if (c < 7)
        out[d * 7 + c] = fmaf(acc, 1.f / (den + EPS), b2[c]);
}

// ---------------- launch (fork-join: CSR build overlaps gemm1) -------------
extern "C" void kernel_launch(void* const* d_in, const int* in_sizes, int n_in,
                              void* d_out, int out_size) {
    const float* x      = (const float*)d_in[0];
    const int*   ei     = (const int*)  d_in[1];
    const float* ew     = (const float*)d_in[2];
    const float* W1     = (const float*)d_in[3];
    const float* a_src1 = (const float*)d_in[4];
    const float* a_dst1 = (const float*)d_in[5];
    const float* b1     = (const float*)d_in[6];
    const float* W2     = (const float*)d_in[7];
    const float* a_src2 = (const float*)d_in[8];
    const float* a_dst2 = (const float*)d_in[9];
    const float* b2     = (const float*)d_in[10];
    float* out = (float*)d_out;

    const int GEMM_SMEM = 128 * 128 * 4 + 128 * 64 * 8;   // 128 KB

    static cudaStream_t s_side = nullptr;
    static cudaEvent_t ev_fork = nullptr, ev_join = nullptr;
    if (!s_side) {
        cudaStreamCreateWithFlags(&s_side, cudaStreamNonBlocking);
        cudaEventCreateWithFlags(&ev_fork, cudaEventDisableTiming);
        cudaEventCreateWithFlags(&ev_join, cudaEventDisableTiming);
        cudaFuncSetAttribute(gemm1_mma_kernel,
                             cudaFuncAttributeMaxDynamicSharedMemorySize,
                             GEMM_SMEM);
    }

    // fork: CSR build chain on side stream (hist -> scan -> scatter)
    cudaEventRecord(ev_fork, 0);
    cudaStreamWaitEvent(s_side, ev_fork, 0);
    hist_kernel<<<((N_EDGES + 3) / 4 + 255) / 256, 256, 0, s_side>>>(ei);
    fused_scan_kernel<<<NSCAN, 256, 0, s_side>>>();
    scatter_kernel<<<(N_TOT + 255) / 256, 256, 0, s_side>>>(ei, ew);
    cudaEventRecord(ev_join, s_side);

    // main stream: GEMM1 via 3xTF32 mma (independent of CSR build)
    gemm1_mma_kernel<<<(N_NODES + 127) / 128, 256, GEMM_SMEM>>>(
        x, W1, a_src1, a_dst1);

    // join, then fused aggregations
    cudaStreamWaitEvent(0, ev_join, 0);
    agg1_csr_kernel<<<(N_NODES * 32 + 511) / 512, 512>>>(b1, W2, a_src2, a_dst2);
    agg2_csr_kernel<<<(N_NODES * 8 + 511) / 512, 512>>>(out, b2);
}

// round 9
// speedup vs baseline: 1.0853x; 1.0853x over previous
#include <cuda_runtime.h>
#include <cuda_fp16.h>
#include <cstdint>

#define N_NODES 100000
#define N_EDGES 1600000
#define N_TOT   1700000           // edges + self loops
#define NEG_SLOPE 0.2f
#define EPS 1e-16f
#define SCAN_B 1024
#define NSCAN ((N_NODES + SCAN_B - 1) / SCAN_B)   // 98

// ---------------- scratch (device globals; no allocation allowed) ----------
__device__ __half2 g_h1h[N_NODES * 32];  // layer-1 features (fp16, gather-only)
__device__ float g_h2[N_NODES * 8];      // layer-2 features (padded 7->8)
__device__ float g_as[N_NODES];          // layer-1 alpha_src per node
__device__ float g_ad[N_NODES];          // layer-1 alpha_dst per node
__device__ float g_as2[N_NODES];         // layer-2 alpha_src per node
__device__ float g_ad2[N_NODES];         // layer-2 alpha_dst per node
__device__ int   g_deg[N_NODES];         // in-degree histogram (zeroed by scan)
__device__ int   g_off[N_NODES + 1];     // CSR row offsets (by dst)
__device__ int   g_cur[N_NODES];         // scatter cursors
__device__ int   g_bsum[NSCAN];          // scan block sums
__device__ int   g_arrive;               // grid-barrier counters (self-reset)
__device__ int   g_depart;
__device__ int2  g_es[N_TOT];            // CSR payload: (src, adj bits)

// ---------------- tf32 helpers ---------------------------------------------
__device__ __forceinline__ uint32_t f2tf32(float f) {
    uint32_t r;
    asm("cvt.rna.tf32.f32 %0, %1;" : "=r"(r) : "f"(f));
    return r;
}

__device__ __forceinline__ void mma16n8k8(float* d,
                                          uint32_t a0, uint32_t a1,
                                          uint32_t a2, uint32_t a3,
                                          uint32_t b0, uint32_t b1) {
    asm volatile(
        "mma.sync.aligned.m16n8k8.row.col.f32.tf32.tf32.f32 "
        "{%0,%1,%2,%3}, {%4,%5,%6,%7}, {%8,%9}, {%0,%1,%2,%3};"
        : "+f"(d[0]), "+f"(d[1]), "+f"(d[2]), "+f"(d[3])
        : "r"(a0), "r"(a1), "r"(a2), "r"(a3), "r"(b0), "r"(b1));
}

// ---------------- K1: h1 = x @ W1 via 3xTF32 mma, fused alphas -------------
// K processed in 2 chunks of 64 through a 64KB smem buffer so 2 CTAs/SM fit;
// W1 pre-split into packed (hi,lo) tf32 at staging (zero B cvts in mainloop).
// B swizzle includes ((k>>1)&1)<<2 to kill LDS.64 half-warp bank conflicts.
__global__ __launch_bounds__(256, 2)
void gemm1_mma_kernel(const float* __restrict__ x,
                      const float* __restrict__ W1,
                      const float* __restrict__ a_src,
                      const float* __restrict__ a_dst) {
    extern __shared__ char smem_raw[];
    float* As  = (float*)smem_raw;                  // 128 x 64 fp32, swizzled
    uint2* Bsp = (uint2*)(smem_raw + 128 * 64 * 4); // 64 x 64 (hi,lo), swizzled
    __shared__ float as_s[64], ad_s[64];

    const int t = threadIdx.x;
    const int rbase = blockIdx.x * 128;

    if (t < 64)       as_s[t]      = a_src[t];
    else if (t < 128) ad_s[t - 64] = a_dst[t - 64];

    const int w    = t >> 5;
    const int lane = t & 31;
    const int g    = lane >> 2;
    const int tg   = lane & 3;
    const int wr   = w * 16;

    float acc[8][4];
#pragma unroll
    for (int i = 0; i < 8; ++i)
#pragma unroll
        for (int j = 0; j < 4; ++j) acc[i][j] = 0.f;

    const int aOff0 = (wr + g) * 64;
    const int aOff1 = aOff0 + 8 * 64;
    const int sA    = g << 2;
    // B bit-2 swizzle term is tg-bit1 on the read side (kb multiple of 8)
    const int bG    = g ^ ((tg >> 1) << 2);

    for (int kc = 0; kc < 2; ++kc) {
        if (kc) __syncthreads();   // drain previous chunk's reads

        // stage As: 128 rows x 64 k (2048 float4)
#pragma unroll
        for (int i = 0; i < 8; ++i) {
            int fid = i * 256 + t;
            int row = fid >> 4;
            int k4  = (fid & 15) * 4;
            int gr  = rbase + row;
            float4 v = make_float4(0.f, 0.f, 0.f, 0.f);
            if (gr < N_NODES) v = *(const float4*)&x[gr * 128 + kc * 64 + k4];
            int ks = k4 ^ ((row & 7) << 2);
            *(float4*)&As[row * 64 + ks] = v;
        }
        // stage Bs: 64 k rows x 64 n, pre-split hi/lo (1024 float4)
#pragma unroll
        for (int i = 0; i < 4; ++i) {
            int fid = i * 256 + t;
            int k  = fid >> 4;              // local k 0..63
            int n4 = (fid & 15) * 4;
            float4 v = *(const float4*)&W1[(kc * 64 + k) * 64 + n4];
            int ns = (n4 ^ ((k & 3) << 3)) ^ (((k >> 1) & 1) << 2);
            uint2* dst = &Bsp[k * 64 + ns];
            float vv[4] = {v.x, v.y, v.z, v.w};
#pragma unroll
            for (int jj = 0; jj < 4; ++jj) {
                uint32_t hi = f2tf32(vv[jj]);
                uint32_t lo = f2tf32(vv[jj] - __uint_as_float(hi));
                dst[jj] = make_uint2(hi, lo);
            }
        }
        __syncthreads();

#pragma unroll
        for (int step = 0; step < 8; ++step) {
            const int kb  = step * 8;
            const int ia0 = (kb + tg) ^ sA;
            float af0 = As[aOff0 + ia0];
            float af1 = As[aOff1 + ia0];
            float af2 = As[aOff0 + (ia0 ^ 4)];
            float af3 = As[aOff1 + (ia0 ^ 4)];
            uint32_t ah0 = f2tf32(af0), ah1 = f2tf32(af1);
            uint32_t ah2 = f2tf32(af2), ah3 = f2tf32(af3);
            uint32_t al0 = f2tf32(af0 - __uint_as_float(ah0));
            uint32_t al1 = f2tf32(af1 - __uint_as_float(ah1));
            uint32_t al2 = f2tf32(af2 - __uint_as_float(ah2));
            uint32_t al3 = f2tf32(af3 - __uint_as_float(ah3));
            const int bRow = (kb + tg) * 64 + bG;
#pragma unroll
            for (int nt = 0; nt < 8; ++nt) {
                int bi0 = bRow + ((nt ^ tg) << 3);
                uint2 b0 = Bsp[bi0];          // k = kb+tg
                uint2 b1 = Bsp[bi0 + 256];    // k = kb+tg+4 (same swizzle bits)
                mma16n8k8(acc[nt], ah0, ah1, ah2, ah3, b0.x, b1.x);
                mma16n8k8(acc[nt], al0, al1, al2, al3, b0.x, b1.x);
                mma16n8k8(acc[nt], ah0, ah1, ah2, ah3, b0.y, b1.y);
            }
        }
    }

    const int r0 = rbase + wr + g;
    const int r1 = r0 + 8;
    float pas0 = 0.f, pad0 = 0.f, pas1 = 0.f, pad1 = 0.f;
#pragma unroll
    for (int nt = 0; nt < 8; ++nt) {
        int c = nt * 8 + 2 * tg;
        float2 av = *(const float2*)&as_s[c];
        float2 dv = *(const float2*)&ad_s[c];
        pas0 += acc[nt][0] * av.x + acc[nt][1] * av.y;
        pad0 += acc[nt][0] * dv.x + acc[nt][1] * dv.y;
        pas1 += acc[nt][2] * av.x + acc[nt][3] * av.y;
        pad1 += acc[nt][2] * dv.x + acc[nt][3] * dv.y;
        if (r0 < N_NODES)
            g_h1h[r0 * 32 + nt * 4 + tg] = __floats2half2_rn(acc[nt][0], acc[nt][1]);
        if (r1 < N_NODES)
            g_h1h[r1 * 32 + nt * 4 + tg] = __floats2half2_rn(acc[nt][2], acc[nt][3]);
    }
#pragma unroll
    for (int off = 1; off <= 2; off <<= 1) {
        pas0 += __shfl_xor_sync(0xffffffffu, pas0, off);
        pad0 += __shfl_xor_sync(0xffffffffu, pad0, off);
        pas1 += __shfl_xor_sync(0xffffffffu, pas1, off);
        pad1 += __shfl_xor_sync(0xffffffffu, pad1, off);
    }
    if (tg == 0) {
        if (r0 < N_NODES) { g_as[r0] = pas0; g_ad[r0] = pad0; }
        if (r1 < N_NODES) { g_as[r1] = pas1; g_ad[r1] = pad1; }
    }
}

// ---------------- CSR build (side stream, overlapped with gemm1) -----------
__global__ void hist_kernel(const int* __restrict__ ei) {
    int t = blockIdx.x * blockDim.x + threadIdx.x;
    int e4 = t * 4;
    if (e4 + 3 < N_EDGES) {
        int4 d4 = *(const int4*)&ei[N_EDGES + e4];
        atomicAdd(&g_deg[d4.x], 1);
        atomicAdd(&g_deg[d4.y], 1);
        atomicAdd(&g_deg[d4.z], 1);
        atomicAdd(&g_deg[d4.w], 1);
    } else {
        for (int e = e4; e < N_EDGES && e < e4 + 4; ++e)
            atomicAdd(&g_deg[ei[N_EDGES + e]], 1);
    }
    if (t < N_NODES) atomicAdd(&g_deg[t], 1);
}

__global__ void fused_scan_kernel() {
    __shared__ int sh[256];
    __shared__ int bs[NSCAN];
    const int tid = threadIdx.x;
    const int b   = blockIdx.x;
    const int base = b * SCAN_B + tid * 4;

    int v[4];
#pragma unroll
    for (int k = 0; k < 4; ++k)
        v[k] = (base + k < N_NODES) ? g_deg[base + k] : 0;
    int local = v[0] + v[1] + v[2] + v[3];
    sh[tid] = local;
    __syncthreads();
    for (int off = 1; off < 256; off <<= 1) {
        int t2 = (tid >= off) ? sh[tid - off] : 0;
        __syncthreads();
        sh[tid] += t2;
        __syncthreads();
    }
    int incl = sh[tid];

    if (tid == 0) {
        g_bsum[b] = sh[255];
        __threadfence();
        atomicAdd(&g_arrive, 1);
        while (*(volatile int*)&g_arrive < NSCAN) { }
    }
    __syncthreads();

    if (tid < NSCAN) bs[tid] = *(volatile int*)&g_bsum[tid];
    __syncthreads();
    int bpre = 0;
    for (int i = 0; i < b; ++i) bpre += bs[i];

    int run = bpre + incl - local;
#pragma unroll
    for (int k = 0; k < 4; ++k) {
        if (base + k < N_NODES) {
            g_off[base + k] = run;
            g_cur[base + k] = run;
            g_deg[base + k] = 0;
        }
        run += v[k];
    }
    if (b == NSCAN - 1 && tid == 255) g_off[N_NODES] = N_TOT;

    __syncthreads();
    if (tid == 0) {
        int old = atomicAdd(&g_depart, 1);
        if (old == NSCAN - 1) { g_depart = 0; g_arrive = 0; }
    }
}

__global__ void scatter_kernel(const int* __restrict__ ei,
                               const float* __restrict__ ew) {
    int e = blockIdx.x * blockDim.x + threadIdx.x;
    if (e >= N_TOT) return;
    int s, d; float adj;
    if (e < N_EDGES) {
        s = ei[e]; d = ei[N_EDGES + e];
        adj = 1.f - 1.f / ew[e];
    } else {
        s = d = e - N_EDGES;
        adj = 0.f;
    }
    int pos = atomicAdd(&g_cur[d], 1);
    g_es[pos] = make_int2(s, __float_as_int(adj));
}

// ---------------- K2: fused layer-1 softmax+aggregate + layer-2 features ----
__global__ void agg1_csr_kernel(const float* __restrict__ b1,
                                const float* __restrict__ W2,
                                const float* __restrict__ a_src2,
                                const float* __restrict__ a_dst2) {
    __shared__ float w2s[448];
    __shared__ float as2s[8], ad2s[8];
    __shared__ float b1s[64];
    int tid = threadIdx.x;
    if (tid < 224) { w2s[tid] = W2[tid]; w2s[tid + 224] = W2[tid + 224]; }
    if (tid < 7)   { as2s[tid] = a_src2[tid]; ad2s[tid] = a_dst2[tid]; }
    if (tid < 64)  b1s[tid] = b1[tid];
    __syncthreads();

    int d    = (blockIdx.x * blockDim.x + tid) >> 5;
    int lane = tid & 31;
    if (d >= N_NODES) return;

    float ad_d = g_ad[d];
    int j = g_off[d], end = g_off[d + 1];
    float den = 0.f, a0 = 0.f, a1 = 0.f;

    for (; j + 7 < end; j += 8) {
        int2 e[8];
#pragma unroll
        for (int q = 0; q < 8; ++q) e[q] = g_es[j + q];
        float sa[8]; __half2 hh[8];
#pragma unroll
        for (int q = 0; q < 8; ++q) {
            sa[q] = g_as[e[q].x];
            hh[q] = g_h1h[e[q].x * 32 + lane];
        }
#pragma unroll
        for (int q = 0; q < 8; ++q) {
            float xx = sa[q] + ad_d; xx = (xx > 0.f) ? xx : NEG_SLOPE * xx;
            float ea = __expf(xx + __int_as_float(e[q].y));
            float2 f = __half22float2(hh[q]);
            den += ea; a0 += ea * f.x; a1 += ea * f.y;
        }
    }
    if (j + 3 < end) {
        int2 e[4];
#pragma unroll
        for (int q = 0; q < 4; ++q) e[q] = g_es[j + q];
        float sa[4]; __half2 hh[4];
#pragma unroll
        for (int q = 0; q < 4; ++q) {
            sa[q] = g_as[e[q].x];
            hh[q] = g_h1h[e[q].x * 32 + lane];
        }
#pragma unroll
        for (int q = 0; q < 4; ++q) {
            float xx = sa[q] + ad_d; xx = (xx > 0.f) ? xx : NEG_SLOPE * xx;
            float ea = __expf(xx + __int_as_float(e[q].y));
            float2 f = __half22float2(hh[q]);
            den += ea; a0 += ea * f.x; a1 += ea * f.y;
        }
        j += 4;
    }
    for (; j < end; ++j) {
        int2 e0 = g_es[j];
        float sa0 = g_as[e0.x];
        __half2 h0 = g_h1h[e0.x * 32 + lane];
        float xx = sa0 + ad_d; xx = (xx > 0.f) ? xx : NEG_SLOPE * xx;
        float ea = __expf(xx + __int_as_float(e0.y));
        float2 f = __half22float2(h0);
        den += ea; a0 += ea * f.x; a1 += ea * f.y;
    }

    float inv = 1.f / (den + EPS);
    float f0 = fmaxf(fmaf(a0, inv, b1s[lane * 2]),     0.f);
    float f1 = fmaxf(fmaf(a1, inv, b1s[lane * 2 + 1]), 0.f);

    float p[7];
#pragma unroll
    for (int c = 0; c < 7; ++c)
        p[c] = f0 * w2s[(lane * 2) * 7 + c] + f1 * w2s[(lane * 2 + 1) * 7 + c];
#pragma unroll
    for (int off = 16; off > 0; off >>= 1)
#pragma unroll
        for (int c = 0; c < 7; ++c)
            p[c] += __shfl_xor_sync(0xffffffffu, p[c], off);

    if (lane == 0) {
        float4 v0 = make_float4(p[0], p[1], p[2], p[3]);
        float4 v1 = make_float4(p[4], p[5], p[6], 0.f);
        *(float4*)&g_h2[d * 8]     = v0;
        *(float4*)&g_h2[d * 8 + 4] = v1;
        float s2 = 0.f, t2 = 0.f;
#pragma unroll
        for (int c = 0; c < 7; ++c) {
            s2 += p[c] * as2s[c];
            t2 += p[c] * ad2s[c];
        }
        g_as2[d] = s2;
        g_ad2[d] = t2;
    }
}

// ---------------- K3: fused layer-2 softmax+aggregate (8 lanes / dst) -------
__global__ void agg2_csr_kernel(float* __restrict__ out,
                                const float* __restrict__ b2) {
    int gt = blockIdx.x * blockDim.x + threadIdx.x;
    int d  = gt >> 3;
    int c  = gt & 7;
    if (d >= N_NODES) return;

    float ad_d = g_ad2[d];
    int j = g_off[d], end = g_off[d + 1];
    float den = 0.f, acc = 0.f;
    for (; j + 3 < end; j += 4) {
        int2 e[4];
#pragma unroll
        for (int q = 0; q < 4; ++q) e[q] = g_es[j + q];
        float sa[4], hv[4];
#pragma unroll
        for (int q = 0; q < 4; ++q) {
            sa[q] = g_as2[e[q].x];
            hv[q] = g_h2[e[q].x * 8 + c];
        }
#pragma unroll
        for (int q = 0; q < 4; ++q) {
            float a = sa[q] + ad_d; a = (a > 0.f) ? a : NEG_SLOPE * a;
            float ea = __expf(a + __int_as_float(e[q].y));
            den += ea; acc += ea * hv[q];
        }
    }
    for (; j < end; ++j) {
        int2 e0 = g_es[j];
        float a = g_as2[e0.x] + ad_d; a = (a > 0.f) ? a : NEG_SLOPE * a;
        float ea = __expf(a + __int_as_float(e0.y));
        den += ea;
        acc += ea * g_h2[e0.x * 8 + c];
    }
    if (c < 7)
        out[d * 7 + c] = fmaf(acc, 1.f / (den + EPS), b2[c]);
}

// ---------------- launch (fork-join: CSR build overlaps gemm1) -------------
extern "C" void kernel_launch(void* const* d_in, const int* in_sizes, int n_in,
                              void* d_out, int out_size) {
    const float* x      = (const float*)d_in[0];
    const int*   ei     = (const int*)  d_in[1];
    const float* ew     = (const float*)d_in[2];
    const float* W1     = (const float*)d_in[3];
    const float* a_src1 = (const float*)d_in[4];
    const float* a_dst1 = (const float*)d_in[5];
    const float* b1     = (const float*)d_in[6];
    const float* W2     = (const float*)d_in[7];
    const float* a_src2 = (const float*)d_in[8];
    const float* a_dst2 = (const float*)d_in[9];
    const float* b2     = (const float*)d_in[10];
    float* out = (float*)d_out;

    const int GEMM_SMEM = 128 * 64 * 4 + 64 * 64 * 8;   // 64 KB

    static cudaStream_t s_side = nullptr;
    static cudaEvent_t ev_fork = nullptr, ev_join = nullptr;
    if (!s_side) {
        cudaStreamCreateWithFlags(&s_side, cudaStreamNonBlocking);
        cudaEventCreateWithFlags(&ev_fork, cudaEventDisableTiming);
        cudaEventCreateWithFlags(&ev_join, cudaEventDisableTiming);
        cudaFuncSetAttribute(gemm1_mma_kernel,
                             cudaFuncAttributeMaxDynamicSharedMemorySize,
                             GEMM_SMEM);
    }

    // fork: CSR build chain on side stream (hist -> scan -> scatter)
    cudaEventRecord(ev_fork, 0);
    cudaStreamWaitEvent(s_side, ev_fork, 0);
    hist_kernel<<<((N_EDGES + 3) / 4 + 255) / 256, 256, 0, s_side>>>(ei);
    fused_scan_kernel<<<NSCAN, 256, 0, s_side>>>();
    scatter_kernel<<<(N_TOT + 255) / 256, 256, 0, s_side>>>(ei, ew);
    cudaEventRecord(ev_join, s_side);

    // main stream: GEMM1 via 3xTF32 mma (independent of CSR build)
    gemm1_mma_kernel<<<(N_NODES + 127) / 128, 256, GEMM_SMEM>>>(
        x, W1, a_src1, a_dst1);

    // join, then fused aggregations
    cudaStreamWaitEvent(0, ev_join, 0);
    agg1_csr_kernel<<<(N_NODES * 32 + 255) / 256, 256>>>(b1, W2, a_src2, a_dst2);
    agg2_csr_kernel<<<(N_NODES * 8 + 255) / 256, 256>>>(out, b2);
}

// round 10
// speedup vs baseline: 1.3275x; 1.2231x over previous
#include <cuda_runtime.h>
#include <cuda_fp16.h>
#include <cstdint>

#define N_NODES 100000
#define N_EDGES 1600000
#define N_TOT   1700000           // edges + self loops
#define NEG_SLOPE 0.2f
#define EPS 1e-16f
#define SCAN_B 1024
#define NSCAN ((N_NODES + SCAN_B - 1) / SCAN_B)   // 98

// ---------------- scratch (device globals; no allocation allowed) ----------
__device__ __half2 g_h1h[N_NODES * 32];  // layer-1 features (fp16, gather-only)
__device__ float g_h2[N_NODES * 8];      // layer-2 features (padded 7->8)
__device__ float g_as[N_NODES];          // layer-1 alpha_src per node
__device__ float g_ad[N_NODES];          // layer-1 alpha_dst per node
__device__ float g_as2[N_NODES];         // layer-2 alpha_src per node
__device__ float g_ad2[N_NODES];         // layer-2 alpha_dst per node
__device__ int   g_deg[N_NODES];         // in-degree histogram (zeroed by scan)
__device__ int   g_off[N_NODES + 1];     // CSR row offsets (by dst)
__device__ int   g_cur[N_NODES];         // scatter cursors
__device__ int   g_bsum[NSCAN];          // scan block sums
__device__ int   g_arrive;               // grid-barrier counters (self-reset)
__device__ int   g_depart;
__device__ int2  g_es[N_TOT];            // CSR payload: (src, adj bits)

// ---------------- tf32 helpers ---------------------------------------------
__device__ __forceinline__ uint32_t f2tf32(float f) {
    uint32_t r;
    asm("cvt.rna.tf32.f32 %0, %1;" : "=r"(r) : "f"(f));
    return r;
}

__device__ __forceinline__ void mma16n8k8(float* d,
                                          uint32_t a0, uint32_t a1,
                                          uint32_t a2, uint32_t a3,
                                          uint32_t b0, uint32_t b1) {
    asm volatile(
        "mma.sync.aligned.m16n8k8.row.col.f32.tf32.tf32.f32 "
        "{%0,%1,%2,%3}, {%4,%5,%6,%7}, {%8,%9}, {%0,%1,%2,%3};"
        : "+f"(d[0]), "+f"(d[1]), "+f"(d[2]), "+f"(d[3])
        : "r"(a0), "r"(a1), "r"(a2), "r"(a3), "r"(b0), "r"(b1));
}

// ---------------- K1: h1 = x @ W1 via 3xTF32 mma, fused alphas -------------
__global__ __launch_bounds__(256, 2)
void gemm1_mma_kernel(const float* __restrict__ x,
                      const float* __restrict__ W1,
                      const float* __restrict__ a_src,
                      const float* __restrict__ a_dst) {
    extern __shared__ char smem_raw[];
    float* As  = (float*)smem_raw;                  // 128 x 64 fp32, swizzled
    uint2* Bsp = (uint2*)(smem_raw + 128 * 64 * 4); // 64 x 64 (hi,lo), swizzled
    __shared__ float as_s[64], ad_s[64];

    const int t = threadIdx.x;
    const int rbase = blockIdx.x * 128;

    if (t < 64)       as_s[t]      = a_src[t];
    else if (t < 128) ad_s[t - 64] = a_dst[t - 64];

    const int w    = t >> 5;
    const int lane = t & 31;
    const int g    = lane >> 2;
    const int tg   = lane & 3;
    const int wr   = w * 16;

    float acc[8][4];
#pragma unroll
    for (int i = 0; i < 8; ++i)
#pragma unroll
        for (int j = 0; j < 4; ++j) acc[i][j] = 0.f;

    const int aOff0 = (wr + g) * 64;
    const int aOff1 = aOff0 + 8 * 64;
    const int sA    = g << 2;
    const int bG    = g ^ ((tg >> 1) << 2);

    for (int kc = 0; kc < 2; ++kc) {
        if (kc) __syncthreads();

#pragma unroll
        for (int i = 0; i < 8; ++i) {
            int fid = i * 256 + t;
            int row = fid >> 4;
            int k4  = (fid & 15) * 4;
            int gr  = rbase + row;
            float4 v = make_float4(0.f, 0.f, 0.f, 0.f);
            if (gr < N_NODES) v = *(const float4*)&x[gr * 128 + kc * 64 + k4];
            int ks = k4 ^ ((row & 7) << 2);
            *(float4*)&As[row * 64 + ks] = v;
        }
#pragma unroll
        for (int i = 0; i < 4; ++i) {
            int fid = i * 256 + t;
            int k  = fid >> 4;
            int n4 = (fid & 15) * 4;
            float4 v = *(const float4*)&W1[(kc * 64 + k) * 64 + n4];
            int ns = (n4 ^ ((k & 3) << 3)) ^ (((k >> 1) & 1) << 2);
            uint2* dst = &Bsp[k * 64 + ns];
            float vv[4] = {v.x, v.y, v.z, v.w};
#pragma unroll
            for (int jj = 0; jj < 4; ++jj) {
                uint32_t hi = f2tf32(vv[jj]);
                uint32_t lo = f2tf32(vv[jj] - __uint_as_float(hi));
                dst[jj] = make_uint2(hi, lo);
            }
        }
        __syncthreads();

#pragma unroll
        for (int step = 0; step < 8; ++step) {
            const int kb  = step * 8;
            const int ia0 = (kb + tg) ^ sA;
            float af0 = As[aOff0 + ia0];
            float af1 = As[aOff1 + ia0];
            float af2 = As[aOff0 + (ia0 ^ 4)];
            float af3 = As[aOff1 + (ia0 ^ 4)];
            uint32_t ah0 = f2tf32(af0), ah1 = f2tf32(af1);
            uint32_t ah2 = f2tf32(af2), ah3 = f2tf32(af3);
            uint32_t al0 = f2tf32(af0 - __uint_as_float(ah0));
            uint32_t al1 = f2tf32(af1 - __uint_as_float(ah1));
            uint32_t al2 = f2tf32(af2 - __uint_as_float(ah2));
            uint32_t al3 = f2tf32(af3 - __uint_as_float(ah3));
            const int bRow = (kb + tg) * 64 + bG;
#pragma unroll
            for (int nt = 0; nt < 8; ++nt) {
                int bi0 = bRow + ((nt ^ tg) << 3);
                uint2 b0 = Bsp[bi0];
                uint2 b1 = Bsp[bi0 + 256];
                mma16n8k8(acc[nt], ah0, ah1, ah2, ah3, b0.x, b1.x);
                mma16n8k8(acc[nt], al0, al1, al2, al3, b0.x, b1.x);
                mma16n8k8(acc[nt], ah0, ah1, ah2, ah3, b0.y, b1.y);
            }
        }
    }

    const int r0 = rbase + wr + g;
    const int r1 = r0 + 8;
    float pas0 = 0.f, pad0 = 0.f, pas1 = 0.f, pad1 = 0.f;
#pragma unroll
    for (int nt = 0; nt < 8; ++nt) {
        int c = nt * 8 + 2 * tg;
        float2 av = *(const float2*)&as_s[c];
        float2 dv = *(const float2*)&ad_s[c];
        pas0 += acc[nt][0] * av.x + acc[nt][1] * av.y;
        pad0 += acc[nt][0] * dv.x + acc[nt][1] * dv.y;
        pas1 += acc[nt][2] * av.x + acc[nt][3] * av.y;
        pad1 += acc[nt][2] * dv.x + acc[nt][3] * dv.y;
        if (r0 < N_NODES)
            g_h1h[r0 * 32 + nt * 4 + tg] = __floats2half2_rn(acc[nt][0], acc[nt][1]);
        if (r1 < N_NODES)
            g_h1h[r1 * 32 + nt * 4 + tg] = __floats2half2_rn(acc[nt][2], acc[nt][3]);
    }
#pragma unroll
    for (int off = 1; off <= 2; off <<= 1) {
        pas0 += __shfl_xor_sync(0xffffffffu, pas0, off);
        pad0 += __shfl_xor_sync(0xffffffffu, pad0, off);
        pas1 += __shfl_xor_sync(0xffffffffu, pas1, off);
        pad1 += __shfl_xor_sync(0xffffffffu, pad1, off);
    }
    if (tg == 0) {
        if (r0 < N_NODES) { g_as[r0] = pas0; g_ad[r0] = pad0; }
        if (r1 < N_NODES) { g_as[r1] = pas1; g_ad[r1] = pad1; }
    }
}

// ---------------- CSR build (side stream, overlapped with gemm1) -----------
__global__ void hist_kernel(const int* __restrict__ ei) {
    int t = blockIdx.x * blockDim.x + threadIdx.x;
    int e4 = t * 4;
    if (e4 + 3 < N_EDGES) {
        int4 d4 = *(const int4*)&ei[N_EDGES + e4];
        atomicAdd(&g_deg[d4.x], 1);
        atomicAdd(&g_deg[d4.y], 1);
        atomicAdd(&g_deg[d4.z], 1);
        atomicAdd(&g_deg[d4.w], 1);
    } else {
        for (int e = e4; e < N_EDGES && e < e4 + 4; ++e)
            atomicAdd(&g_deg[ei[N_EDGES + e]], 1);
    }
    if (t < N_NODES) atomicAdd(&g_deg[t], 1);
}

__global__ void fused_scan_kernel() {
    __shared__ int sh[256];
    __shared__ int bs[NSCAN];
    const int tid = threadIdx.x;
    const int b   = blockIdx.x;
    const int base = b * SCAN_B + tid * 4;

    int v[4];
#pragma unroll
    for (int k = 0; k < 4; ++k)
        v[k] = (base + k < N_NODES) ? g_deg[base + k] : 0;
    int local = v[0] + v[1] + v[2] + v[3];
    sh[tid] = local;
    __syncthreads();
    for (int off = 1; off < 256; off <<= 1) {
        int t2 = (tid >= off) ? sh[tid - off] : 0;
        __syncthreads();
        sh[tid] += t2;
        __syncthreads();
    }
    int incl = sh[tid];

    if (tid == 0) {
        g_bsum[b] = sh[255];
        __threadfence();
        atomicAdd(&g_arrive, 1);
        while (*(volatile int*)&g_arrive < NSCAN) { }
    }
    __syncthreads();

    if (tid < NSCAN) bs[tid] = *(volatile int*)&g_bsum[tid];
    __syncthreads();
    int bpre = 0;
    for (int i = 0; i < b; ++i) bpre += bs[i];

    int run = bpre + incl - local;
#pragma unroll
    for (int k = 0; k < 4; ++k) {
        if (base + k < N_NODES) {
            g_off[base + k] = run;
            g_cur[base + k] = run;
            g_deg[base + k] = 0;
        }
        run += v[k];
    }
    if (b == NSCAN - 1 && tid == 255) g_off[N_NODES] = N_TOT;

    __syncthreads();
    if (tid == 0) {
        int old = atomicAdd(&g_depart, 1);
        if (old == NSCAN - 1) { g_depart = 0; g_arrive = 0; }
    }
}

__global__ void scatter_kernel(const int* __restrict__ ei,
                               const float* __restrict__ ew) {
    int e = blockIdx.x * blockDim.x + threadIdx.x;
    if (e >= N_TOT) return;
    int s, d; float adj;
    if (e < N_EDGES) {
        s = ei[e]; d = ei[N_EDGES + e];
        adj = 1.f - 1.f / ew[e];
    } else {
        s = d = e - N_EDGES;
        adj = 0.f;
    }
    int pos = atomicAdd(&g_cur[d], 1);
    g_es[pos] = make_int2(s, __float_as_int(adj));
}

// ---------------- K2: fused layer-1 softmax+aggregate + layer-2 features ----
// 4 dst nodes per warp, 8 lanes (8 feats each via uint4-of-half2) per node.
// 100000 nodes = 3125 blocks x 32 nodes exactly (no tail -> uniform shuffles).
__global__ void agg1_csr_kernel(const float* __restrict__ b1,
                                const float* __restrict__ W2,
                                const float* __restrict__ a_src2,
                                const float* __restrict__ a_dst2) {
    __shared__ float w2s[448];
    __shared__ float as2s[8], ad2s[8];
    __shared__ float b1s[64];
    int tid = threadIdx.x;
    if (tid < 224) { w2s[tid] = W2[tid]; w2s[tid + 224] = W2[tid + 224]; }
    if (tid < 7)   { as2s[tid] = a_src2[tid]; ad2s[tid] = a_dst2[tid]; }
    if (tid < 64)  b1s[tid] = b1[tid];
    __syncthreads();

    const int w    = tid >> 5;
    const int lane = tid & 31;
    const int sl   = lane & 7;               // lane within 8-lane subgroup
    const int d    = blockIdx.x * 32 + w * 4 + (lane >> 3);

    const float ad_d = g_ad[d];
    int j = g_off[d];
    const int end = g_off[d + 1];
    float den = 0.f;
    float acc[8];
#pragma unroll
    for (int k = 0; k < 8; ++k) acc[k] = 0.f;
    const uint4* h1p = (const uint4*)g_h1h;   // one row = 8 uint4 (64 feats)

    for (; j + 1 < end; j += 2) {
        int2 e0 = g_es[j], e1 = g_es[j + 1];
        float sa0 = g_as[e0.x], sa1 = g_as[e1.x];
        uint4 hv0 = h1p[e0.x * 8 + sl];
        uint4 hv1 = h1p[e1.x * 8 + sl];
        float x0 = sa0 + ad_d; x0 = (x0 > 0.f) ? x0 : NEG_SLOPE * x0;
        float x1 = sa1 + ad_d; x1 = (x1 > 0.f) ? x1 : NEG_SLOPE * x1;
        float ea0 = __expf(x0 + __int_as_float(e0.y));
        float ea1 = __expf(x1 + __int_as_float(e1.y));
        den += ea0 + ea1;
        float2 f;
        f = __half22float2(*(__half2*)&hv0.x); acc[0] += ea0 * f.x; acc[1] += ea0 * f.y;
        f = __half22float2(*(__half2*)&hv0.y); acc[2] += ea0 * f.x; acc[3] += ea0 * f.y;
        f = __half22float2(*(__half2*)&hv0.z); acc[4] += ea0 * f.x; acc[5] += ea0 * f.y;
        f = __half22float2(*(__half2*)&hv0.w); acc[6] += ea0 * f.x; acc[7] += ea0 * f.y;
        f = __half22float2(*(__half2*)&hv1.x); acc[0] += ea1 * f.x; acc[1] += ea1 * f.y;
        f = __half22float2(*(__half2*)&hv1.y); acc[2] += ea1 * f.x; acc[3] += ea1 * f.y;
        f = __half22float2(*(__half2*)&hv1.z); acc[4] += ea1 * f.x; acc[5] += ea1 * f.y;
        f = __half22float2(*(__half2*)&hv1.w); acc[6] += ea1 * f.x; acc[7] += ea1 * f.y;
    }
    if (j < end) {
        int2 e0 = g_es[j];
        float sa0 = g_as[e0.x];
        uint4 hv0 = h1p[e0.x * 8 + sl];
        float x0 = sa0 + ad_d; x0 = (x0 > 0.f) ? x0 : NEG_SLOPE * x0;
        float ea0 = __expf(x0 + __int_as_float(e0.y));
        den += ea0;
        float2 f;
        f = __half22float2(*(__half2*)&hv0.x); acc[0] += ea0 * f.x; acc[1] += ea0 * f.y;
        f = __half22float2(*(__half2*)&hv0.y); acc[2] += ea0 * f.x; acc[3] += ea0 * f.y;
        f = __half22float2(*(__half2*)&hv0.z); acc[4] += ea0 * f.x; acc[5] += ea0 * f.y;
        f = __half22float2(*(__half2*)&hv0.w); acc[6] += ea0 * f.x; acc[7] += ea0 * f.y;
    }

    // epilogue: bias + relu + GEMM2 partials over this lane's 8 feats
    const float inv = 1.f / (den + EPS);
    float p[7];
#pragma unroll
    for (int c = 0; c < 7; ++c) p[c] = 0.f;
#pragma unroll
    for (int k = 0; k < 8; ++k) {
        float fv = fmaxf(fmaf(acc[k], inv, b1s[sl * 8 + k]), 0.f);
        const float* wrow = &w2s[(sl * 8 + k) * 7];
#pragma unroll
        for (int c = 0; c < 7; ++c) p[c] += fv * wrow[c];
    }
    // reduce across the 8-lane subgroup
#pragma unroll
    for (int off = 1; off <= 4; off <<= 1)
#pragma unroll
        for (int c = 0; c < 7; ++c)
            p[c] += __shfl_xor_sync(0xffffffffu, p[c], off);

    if (sl == 0) {
        float4 v0 = make_float4(p[0], p[1], p[2], p[3]);
        float4 v1 = make_float4(p[4], p[5], p[6], 0.f);
        *(float4*)&g_h2[d * 8]     = v0;
        *(float4*)&g_h2[d * 8 + 4] = v1;
        float s2 = 0.f, t2 = 0.f;
#pragma unroll
        for (int c = 0; c < 7; ++c) {
            s2 += p[c] * as2s[c];
            t2 += p[c] * ad2s[c];
        }
        g_as2[d] = s2;
        g_ad2[d] = t2;
    }
}

// ---------------- K3: fused layer-2 softmax+aggregate (8 lanes / dst) -------
__global__ void agg2_csr_kernel(float* __restrict__ out,
                                const float* __restrict__ b2) {
    int gt = blockIdx.x * blockDim.x + threadIdx.x;
    int d  = gt >> 3;
    int c  = gt & 7;
    if (d >= N_NODES) return;

    float ad_d = g_ad2[d];
    int j = g_off[d], end = g_off[d + 1];
    float den = 0.f, acc = 0.f;
    for (; j + 3 < end; j += 4) {
        int2 e[4];
#pragma unroll
        for (int q = 0; q < 4; ++q) e[q] = g_es[j + q];
        float sa[4], hv[4];
#pragma unroll
        for (int q = 0; q < 4; ++q) {
            sa[q] = g_as2[e[q].x];
            hv[q] = g_h2[e[q].x * 8 + c];
        }
#pragma unroll
        for (int q = 0; q < 4; ++q) {
            float a = sa[q] + ad_d; a = (a > 0.f) ? a : NEG_SLOPE * a;
            float ea = __expf(a + __int_as_float(e[q].y));
            den += ea; acc += ea * hv[q];
        }
    }
    for (; j < end; ++j) {
        int2 e0 = g_es[j];
        float a = g_as2[e0.x] + ad_d; a = (a > 0.f) ? a : NEG_SLOPE * a;
        float ea = __expf(a + __int_as_float(e0.y));
        den += ea;
        acc += ea * g_h2[e0.x * 8 + c];
    }
    if (c < 7)
        out[d * 7 + c] = fmaf(acc, 1.f / (den + EPS), b2[c]);
}

// ---------------- launch (fork-join: CSR build overlaps gemm1) -------------
extern "C" void kernel_launch(void* const* d_in, const int* in_sizes, int n_in,
                              void* d_out, int out_size) {
    const float* x      = (const float*)d_in[0];
    const int*   ei     = (const int*)  d_in[1];
    const float* ew     = (const float*)d_in[2];
    const float* W1     = (const float*)d_in[3];
    const float* a_src1 = (const float*)d_in[4];
    const float* a_dst1 = (const float*)d_in[5];
    const float* b1     = (const float*)d_in[6];
    const float* W2     = (const float*)d_in[7];
    const float* a_src2 = (const float*)d_in[8];
    const float* a_dst2 = (const float*)d_in[9];
    const float* b2     = (const float*)d_in[10];
    float* out = (float*)d_out;

    const int GEMM_SMEM = 128 * 64 * 4 + 64 * 64 * 8;   // 64 KB

    static cudaStream_t s_side = nullptr;
    static cudaEvent_t ev_fork = nullptr, ev_join = nullptr;
    if (!s_side) {
        cudaStreamCreateWithFlags(&s_side, cudaStreamNonBlocking);
        cudaEventCreateWithFlags(&ev_fork, cudaEventDisableTiming);
        cudaEventCreateWithFlags(&ev_join, cudaEventDisableTiming);
        cudaFuncSetAttribute(gemm1_mma_kernel,
                             cudaFuncAttributeMaxDynamicSharedMemorySize,
                             GEMM_SMEM);
    }

    // fork: CSR build chain on side stream (hist -> scan -> scatter)
    cudaEventRecord(ev_fork, 0);
    cudaStreamWaitEvent(s_side, ev_fork, 0);
    hist_kernel<<<((N_EDGES + 3) / 4 + 255) / 256, 256, 0, s_side>>>(ei);
    fused_scan_kernel<<<NSCAN, 256, 0, s_side>>>();
    scatter_kernel<<<(N_TOT + 255) / 256, 256, 0, s_side>>>(ei, ew);
    cudaEventRecord(ev_join, s_side);

    // main stream: GEMM1 via 3xTF32 mma (independent of CSR build)
    gemm1_mma_kernel<<<(N_NODES + 127) / 128, 256, GEMM_SMEM>>>(
        x, W1, a_src1, a_dst1);

    // join, then fused aggregations
    cudaStreamWaitEvent(0, ev_join, 0);
    agg1_csr_kernel<<<N_NODES / 32, 256>>>(b1, W2, a_src2, a_dst2);
    agg2_csr_kernel<<<(N_NODES * 8 + 255) / 256, 256>>>(out, b2);
}

// round 11
// speedup vs baseline: 1.4160x; 1.0666x over previous
#include <cuda_runtime.h>
#include <cuda_fp16.h>
#include <cstdint>

#define N_NODES 100000
#define N_EDGES 1600000
#define N_TOT   1700000           // edges + self loops
#define NEG_SLOPE 0.2f
#define EPS 1e-16f
#define SCAN_B 1024
#define NSCAN ((N_NODES + SCAN_B - 1) / SCAN_B)   // 98

// ---------------- scratch (device globals; no allocation allowed) ----------
__device__ __half2 g_h1h[N_NODES * 32];  // layer-1 features (fp16, gather-only)
__device__ float g_h2[N_NODES * 8];      // layer-2 features (padded 7->8)
__device__ float g_as[N_NODES];          // layer-1 alpha_src per node
__device__ float g_ad[N_NODES];          // layer-1 alpha_dst per node
__device__ float g_as2[N_NODES];         // layer-2 alpha_src per node
__device__ float g_ad2[N_NODES];         // layer-2 alpha_dst per node
__device__ int   g_deg[N_NODES];         // in-degree histogram (zeroed by scan)
__device__ int   g_off[N_NODES + 1];     // CSR row offsets (by dst)
__device__ int   g_cur[N_NODES];         // scatter cursors
__device__ int   g_bsum[NSCAN];          // scan block sums
__device__ int   g_arrive;               // grid-barrier counters (self-reset)
__device__ int   g_depart;
__device__ int2  g_es[N_TOT];            // CSR payload: (src, adj bits)

// ---------------- fp16 mma helper ------------------------------------------
__device__ __forceinline__ void mma16n8k16_f16(float* d,
                                               uint32_t a0, uint32_t a1,
                                               uint32_t a2, uint32_t a3,
                                               uint32_t b0, uint32_t b1) {
    asm volatile(
        "mma.sync.aligned.m16n8k16.row.col.f32.f16.f16.f32 "
        "{%0,%1,%2,%3}, {%4,%5,%6,%7}, {%8,%9}, {%0,%1,%2,%3};"
        : "+f"(d[0]), "+f"(d[1]), "+f"(d[2]), "+f"(d[3])
        : "r"(a0), "r"(a1), "r"(a2), "r"(a3), "r"(b0), "r"(b1));
}

__device__ __forceinline__ uint2 split_pack(float v0, float v1) {
    __half h0 = __float2half_rn(v0), h1 = __float2half_rn(v1);
    __half l0 = __float2half_rn(v0 - __half2float(h0));
    __half l1 = __float2half_rn(v1 - __half2float(h1));
    __half2 hi2 = __halves2half2(h0, h1);
    __half2 lo2 = __halves2half2(l0, l1);
    return make_uint2(*(uint32_t*)&hi2, *(uint32_t*)&lo2);
}

// ---------------- K1: h1 = x @ W1 via 3x-FP16 (hi/lo) mma, fused alphas ----
// Both operands pre-split into packed (hi,lo) fp16 pairs at staging; mainloop
// is pure LDS + MMA. K in 2 chunks of 64 (4 k16-steps each). ~50KB smem.
#define B_STRIDE 68   // 64 + 4 uint2 pad -> conflict-free (bank = 8*tg+2g+16nt)
__global__ __launch_bounds__(256, 2)
void gemm1_mma_kernel(const float* __restrict__ x,
                      const float* __restrict__ W1,
                      const float* __restrict__ a_src,
                      const float* __restrict__ a_dst) {
    extern __shared__ char smem_raw[];
    uint2* As = (uint2*)smem_raw;                    // [128][32] (hi2,lo2)
    uint2* Bs = (uint2*)(smem_raw + 128 * 32 * 8);   // [32][B_STRIDE]
    __shared__ float as_s[64], ad_s[64];

    const int t = threadIdx.x;
    const int rbase = blockIdx.x * 128;

    if (t < 64)       as_s[t]      = a_src[t];
    else if (t < 128) ad_s[t - 64] = a_dst[t - 64];

    const int w    = t >> 5;
    const int lane = t & 31;
    const int g    = lane >> 2;
    const int tg   = lane & 3;
    const int wr   = w * 16;

    float acc[8][4];
#pragma unroll
    for (int i = 0; i < 8; ++i)
#pragma unroll
        for (int j = 0; j < 4; ++j) acc[i][j] = 0.f;

    const int rowA  = wr + g;
    const int aSw   = (rowA & 3) << 2;        // same for rowA+8

    for (int kc = 0; kc < 2; ++kc) {
        if (kc) __syncthreads();

        // stage A: 128 rows x 32 k2 (pairs of k), hi/lo split, swizzled
#pragma unroll
        for (int i = 0; i < 16; ++i) {
            int fid = i * 256 + t;
            int row = fid >> 5, k2 = fid & 31;
            int gr  = rbase + row;
            float2 v = make_float2(0.f, 0.f);
            if (gr < N_NODES) v = *(const float2*)&x[gr * 128 + kc * 64 + k2 * 2];
            As[row * 32 + (k2 ^ ((row & 3) << 2))] = split_pack(v.x, v.y);
        }
        // stage B: 32 k2 x 64 n, hi/lo split, padded rows
#pragma unroll
        for (int i = 0; i < 8; ++i) {
            int fid = i * 256 + t;
            int k2 = fid >> 6, n = fid & 63;
            float v0 = W1[(kc * 64 + k2 * 2)     * 64 + n];
            float v1 = W1[(kc * 64 + k2 * 2 + 1) * 64 + n];
            Bs[k2 * B_STRIDE + n] = split_pack(v0, v1);
        }
        __syncthreads();

#pragma unroll
        for (int step = 0; step < 4; ++step) {
            const int k2a = step * 8 + tg;
            uint2 A0 = As[rowA * 32       + (k2a ^ aSw)];
            uint2 A1 = As[(rowA + 8) * 32 + (k2a ^ aSw)];
            uint2 A2 = As[rowA * 32       + ((k2a + 4) ^ aSw)];
            uint2 A3 = As[(rowA + 8) * 32 + ((k2a + 4) ^ aSw)];
            const int bRow0 = k2a * B_STRIDE + g;
            const int bRow1 = (k2a + 4) * B_STRIDE + g;
#pragma unroll
            for (int nt = 0; nt < 8; ++nt) {
                uint2 B0 = Bs[bRow0 + nt * 8];
                uint2 B1 = Bs[bRow1 + nt * 8];
                mma16n8k16_f16(acc[nt], A0.x, A1.x, A2.x, A3.x, B0.x, B1.x); // hi*hi
                mma16n8k16_f16(acc[nt], A0.y, A1.y, A2.y, A3.y, B0.x, B1.x); // lo*hi
                mma16n8k16_f16(acc[nt], A0.x, A1.x, A2.x, A3.x, B0.y, B1.y); // hi*lo
            }
        }
    }

    // epilogue: fp16 h1 store + fused alpha dot products (same C layout)
    const int r0 = rbase + wr + g;
    const int r1 = r0 + 8;
    float pas0 = 0.f, pad0 = 0.f, pas1 = 0.f, pad1 = 0.f;
#pragma unroll
    for (int nt = 0; nt < 8; ++nt) {
        int c = nt * 8 + 2 * tg;
        float2 av = *(const float2*)&as_s[c];
        float2 dv = *(const float2*)&ad_s[c];
        pas0 += acc[nt][0] * av.x + acc[nt][1] * av.y;
        pad0 += acc[nt][0] * dv.x + acc[nt][1] * dv.y;
        pas1 += acc[nt][2] * av.x + acc[nt][3] * av.y;
        pad1 += acc[nt][2] * dv.x + acc[nt][3] * dv.y;
        if (r0 < N_NODES)
            g_h1h[r0 * 32 + nt * 4 + tg] = __floats2half2_rn(acc[nt][0], acc[nt][1]);
        if (r1 < N_NODES)
            g_h1h[r1 * 32 + nt * 4 + tg] = __floats2half2_rn(acc[nt][2], acc[nt][3]);
    }
#pragma unroll
    for (int off = 1; off <= 2; off <<= 1) {
        pas0 += __shfl_xor_sync(0xffffffffu, pas0, off);
        pad0 += __shfl_xor_sync(0xffffffffu, pad0, off);
        pas1 += __shfl_xor_sync(0xffffffffu, pas1, off);
        pad1 += __shfl_xor_sync(0xffffffffu, pad1, off);
    }
    if (tg == 0) {
        if (r0 < N_NODES) { g_as[r0] = pas0; g_ad[r0] = pad0; }
        if (r1 < N_NODES) { g_as[r1] = pas1; g_ad[r1] = pad1; }
    }
}

// ---------------- CSR build (side stream, overlapped with gemm1) -----------
__global__ void hist_kernel(const int* __restrict__ ei) {
    int t = blockIdx.x * blockDim.x + threadIdx.x;
    int e4 = t * 4;
    if (e4 + 3 < N_EDGES) {
        int4 d4 = *(const int4*)&ei[N_EDGES + e4];
        atomicAdd(&g_deg[d4.x], 1);
        atomicAdd(&g_deg[d4.y], 1);
        atomicAdd(&g_deg[d4.z], 1);
        atomicAdd(&g_deg[d4.w], 1);
    } else {
        for (int e = e4; e < N_EDGES && e < e4 + 4; ++e)
            atomicAdd(&g_deg[ei[N_EDGES + e]], 1);
    }
    if (t < N_NODES) atomicAdd(&g_deg[t], 1);
}

__global__ void fused_scan_kernel() {
    __shared__ int sh[256];
    __shared__ int bs[NSCAN];
    const int tid = threadIdx.x;
    const int b   = blockIdx.x;
    const int base = b * SCAN_B + tid * 4;

    int v[4];
#pragma unroll
    for (int k = 0; k < 4; ++k)
        v[k] = (base + k < N_NODES) ? g_deg[base + k] : 0;
    int local = v[0] + v[1] + v[2] + v[3];
    sh[tid] = local;
    __syncthreads();
    for (int off = 1; off < 256; off <<= 1) {
        int t2 = (tid >= off) ? sh[tid - off] : 0;
        __syncthreads();
        sh[tid] += t2;
        __syncthreads();
    }
    int incl = sh[tid];

    if (tid == 0) {
        g_bsum[b] = sh[255];
        __threadfence();
        atomicAdd(&g_arrive, 1);
        while (*(volatile int*)&g_arrive < NSCAN) { }
    }
    __syncthreads();

    if (tid < NSCAN) bs[tid] = *(volatile int*)&g_bsum[tid];
    __syncthreads();
    int bpre = 0;
    for (int i = 0; i < b; ++i) bpre += bs[i];

    int run = bpre + incl - local;
#pragma unroll
    for (int k = 0; k < 4; ++k) {
        if (base + k < N_NODES) {
            g_off[base + k] = run;
            g_cur[base + k] = run;
            g_deg[base + k] = 0;
        }
        run += v[k];
    }
    if (b == NSCAN - 1 && tid == 255) g_off[N_NODES] = N_TOT;

    __syncthreads();
    if (tid == 0) {
        int old = atomicAdd(&g_depart, 1);
        if (old == NSCAN - 1) { g_depart = 0; g_arrive = 0; }
    }
}

__global__ void scatter_kernel(const int* __restrict__ ei,
                               const float* __restrict__ ew) {
    int e = blockIdx.x * blockDim.x + threadIdx.x;
    if (e >= N_TOT) return;
    int s, d; float adj;
    if (e < N_EDGES) {
        s = ei[e]; d = ei[N_EDGES + e];
        adj = 1.f - 1.f / ew[e];
    } else {
        s = d = e - N_EDGES;
        adj = 0.f;
    }
    int pos = atomicAdd(&g_cur[d], 1);
    g_es[pos] = make_int2(s, __float_as_int(adj));
}

// ---------------- K2: fused layer-1 softmax+aggregate + layer-2 features ----
// 4 dst nodes per warp, 8 lanes (8 feats each via uint4-of-half2) per node.
__global__ void agg1_csr_kernel(const float* __restrict__ b1,
                                const float* __restrict__ W2,
                                const float* __restrict__ a_src2,
                                const float* __restrict__ a_dst2) {
    __shared__ float w2s[448];
    __shared__ float as2s[8], ad2s[8];
    __shared__ float b1s[64];
    int tid = threadIdx.x;
    if (tid < 224) { w2s[tid] = W2[tid]; w2s[tid + 224] = W2[tid + 224]; }
    if (tid < 7)   { as2s[tid] = a_src2[tid]; ad2s[tid] = a_dst2[tid]; }
    if (tid < 64)  b1s[tid] = b1[tid];
    __syncthreads();

    const int w    = tid >> 5;
    const int lane = tid & 31;
    const int sl   = lane & 7;
    const int d    = blockIdx.x * 32 + w * 4 + (lane >> 3);

    const float ad_d = g_ad[d];
    int j = g_off[d];
    const int end = g_off[d + 1];
    float den = 0.f;
    float acc[8];
#pragma unroll
    for (int k = 0; k < 8; ++k) acc[k] = 0.f;
    const uint4* h1p = (const uint4*)g_h1h;

    for (; j + 1 < end; j += 2) {
        int2 e0 = g_es[j], e1 = g_es[j + 1];
        float sa0 = g_as[e0.x], sa1 = g_as[e1.x];
        uint4 hv0 = h1p[e0.x * 8 + sl];
        uint4 hv1 = h1p[e1.x * 8 + sl];
        float x0 = sa0 + ad_d; x0 = (x0 > 0.f) ? x0 : NEG_SLOPE * x0;
        float x1 = sa1 + ad_d; x1 = (x1 > 0.f) ? x1 : NEG_SLOPE * x1;
        float ea0 = __expf(x0 + __int_as_float(e0.y));
        float ea1 = __expf(x1 + __int_as_float(e1.y));
        den += ea0 + ea1;
        float2 f;
        f = __half22float2(*(__half2*)&hv0.x); acc[0] += ea0 * f.x; acc[1] += ea0 * f.y;
        f = __half22float2(*(__half2*)&hv0.y); acc[2] += ea0 * f.x; acc[3] += ea0 * f.y;
        f = __half22float2(*(__half2*)&hv0.z); acc[4] += ea0 * f.x; acc[5] += ea0 * f.y;
        f = __half22float2(*(__half2*)&hv0.w); acc[6] += ea0 * f.x; acc[7] += ea0 * f.y;
        f = __half22float2(*(__half2*)&hv1.x); acc[0] += ea1 * f.x; acc[1] += ea1 * f.y;
        f = __half22float2(*(__half2*)&hv1.y); acc[2] += ea1 * f.x; acc[3] += ea1 * f.y;
        f = __half22float2(*(__half2*)&hv1.z); acc[4] += ea1 * f.x; acc[5] += ea1 * f.y;
        f = __half22float2(*(__half2*)&hv1.w); acc[6] += ea1 * f.x; acc[7] += ea1 * f.y;
    }
    if (j < end) {
        int2 e0 = g_es[j];
        float sa0 = g_as[e0.x];
        uint4 hv0 = h1p[e0.x * 8 + sl];
        float x0 = sa0 + ad_d; x0 = (x0 > 0.f) ? x0 : NEG_SLOPE * x0;
        float ea0 = __expf(x0 + __int_as_float(e0.y));
        den += ea0;
        float2 f;
        f = __half22float2(*(__half2*)&hv0.x); acc[0] += ea0 * f.x; acc[1] += ea0 * f.y;
        f = __half22float2(*(__half2*)&hv0.y); acc[2] += ea0 * f.x; acc[3] += ea0 * f.y;
        f = __half22float2(*(__half2*)&hv0.z); acc[4] += ea0 * f.x; acc[5] += ea0 * f.y;
        f = __half22float2(*(__half2*)&hv0.w); acc[6] += ea0 * f.x; acc[7] += ea0 * f.y;
    }

    const float inv = 1.f / (den + EPS);
    float p[7];
#pragma unroll
    for (int c = 0; c < 7; ++c) p[c] = 0.f;
#pragma unroll
    for (int k = 0; k < 8; ++k) {
        float fv = fmaxf(fmaf(acc[k], inv, b1s[sl * 8 + k]), 0.f);
        const float* wrow = &w2s[(sl * 8 + k) * 7];
#pragma unroll
        for (int c = 0; c < 7; ++c) p[c] += fv * wrow[c];
    }
#pragma unroll
    for (int off = 1; off <= 4; off <<= 1)
#pragma unroll
        for (int c = 0; c < 7; ++c)
            p[c] += __shfl_xor_sync(0xffffffffu, p[c], off);

    if (sl == 0) {
        float4 v0 = make_float4(p[0], p[1], p[2], p[3]);
        float4 v1 = make_float4(p[4], p[5], p[6], 0.f);
        *(float4*)&g_h2[d * 8]     = v0;
        *(float4*)&g_h2[d * 8 + 4] = v1;
        float s2 = 0.f, t2 = 0.f;
#pragma unroll
        for (int c = 0; c < 7; ++c) {
            s2 += p[c] * as2s[c];
            t2 += p[c] * ad2s[c];
        }
        g_as2[d] = s2;
        g_ad2[d] = t2;
    }
}

// ---------------- K3: fused layer-2 softmax+aggregate (8 lanes / dst) -------
__global__ void agg2_csr_kernel(float* __restrict__ out,
                                const float* __restrict__ b2) {
    int gt = blockIdx.x * blockDim.x + threadIdx.x;
    int d  = gt >> 3;
    int c  = gt & 7;
    if (d >= N_NODES) return;

    float ad_d = g_ad2[d];
    int j = g_off[d], end = g_off[d + 1];
    float den = 0.f, acc = 0.f;
    for (; j + 3 < end; j += 4) {
        int2 e[4];
#pragma unroll
        for (int q = 0; q < 4; ++q) e[q] = g_es[j + q];
        float sa[4], hv[4];
#pragma unroll
        for (int q = 0; q < 4; ++q) {
            sa[q] = g_as2[e[q].x];
            hv[q] = g_h2[e[q].x * 8 + c];
        }
#pragma unroll
        for (int q = 0; q < 4; ++q) {
            float a = sa[q] + ad_d; a = (a > 0.f) ? a : NEG_SLOPE * a;
            float ea = __expf(a + __int_as_float(e[q].y));
            den += ea; acc += ea * hv[q];
        }
    }
    for (; j < end; ++j) {
        int2 e0 = g_es[j];
        float a = g_as2[e0.x] + ad_d; a = (a > 0.f) ? a : NEG_SLOPE * a;
        float ea = __expf(a + __int_as_float(e0.y));
        den += ea;
        acc += ea * g_h2[e0.x * 8 + c];
    }
    if (c < 7)
        out[d * 7 + c] = fmaf(acc, 1.f / (den + EPS), b2[c]);
}

// ---------------- launch (fork-join: CSR build overlaps gemm1) -------------
extern "C" void kernel_launch(void* const* d_in, const int* in_sizes, int n_in,
                              void* d_out, int out_size) {
    const float* x      = (const float*)d_in[0];
    const int*   ei     = (const int*)  d_in[1];
    const float* ew     = (const float*)d_in[2];
    const float* W1     = (const float*)d_in[3];
    const float* a_src1 = (const float*)d_in[4];
    const float* a_dst1 = (const float*)d_in[5];
    const float* b1     = (const float*)d_in[6];
    const float* W2     = (const float*)d_in[7];
    const float* a_src2 = (const float*)d_in[8];
    const float* a_dst2 = (const float*)d_in[9];
    const float* b2     = (const float*)d_in[10];
    float* out = (float*)d_out;

    const int GEMM_SMEM = 128 * 32 * 8 + 32 * B_STRIDE * 8;   // ~50 KB

    static cudaStream_t s_side = nullptr;
    static cudaEvent_t ev_fork = nullptr, ev_join = nullptr;
    if (!s_side) {
        cudaStreamCreateWithFlags(&s_side, cudaStreamNonBlocking);
        cudaEventCreateWithFlags(&ev_fork, cudaEventDisableTiming);
        cudaEventCreateWithFlags(&ev_join, cudaEventDisableTiming);
        cudaFuncSetAttribute(gemm1_mma_kernel,
                             cudaFuncAttributeMaxDynamicSharedMemorySize,
                             GEMM_SMEM);
    }

    // fork: CSR build chain on side stream (hist -> scan -> scatter)
    cudaEventRecord(ev_fork, 0);
    cudaStreamWaitEvent(s_side, ev_fork, 0);
    hist_kernel<<<((N_EDGES + 3) / 4 + 255) / 256, 256, 0, s_side>>>(ei);
    fused_scan_kernel<<<NSCAN, 256, 0, s_side>>>();
    scatter_kernel<<<(N_TOT + 255) / 256, 256, 0, s_side>>>(ei, ew);
    cudaEventRecord(ev_join, s_side);

    // main stream: GEMM1 via 3x-FP16 mma (independent of CSR build)
    gemm1_mma_kernel<<<(N_NODES + 127) / 128, 256, GEMM_SMEM>>>(
        x, W1, a_src1, a_dst1);

    // join, then fused aggregations
    cudaStreamWaitEvent(0, ev_join, 0);
    agg1_csr_kernel<<<N_NODES / 32, 256>>>(b1, W2, a_src2, a_dst2);
    agg2_csr_kernel<<<(N_NODES * 8 + 255) / 256, 256>>>(out, b2);
}

// round 12
// speedup vs baseline: 1.4214x; 1.0038x over previous
#include <cuda_runtime.h>
#include <cuda_fp16.h>
#include <cstdint>

#define N_NODES 100000
#define N_EDGES 1600000
#define N_TOT   1700000           // edges + self loops
#define NEG_SLOPE 0.2f
#define EPS 1e-16f
#define SCAN_B 1024
#define NSCAN ((N_NODES + SCAN_B - 1) / SCAN_B)   // 98

// ---------------- scratch (device globals; no allocation allowed) ----------
__device__ __half2 g_h1h[N_NODES * 32];  // layer-1 features (fp16, gather-only)
__device__ float g_h2[N_NODES * 8];      // layer-2 features (padded 7->8)
__device__ float g_as[N_NODES];          // layer-1 alpha_src per node
__device__ float g_ad[N_NODES];          // layer-1 alpha_dst per node
__device__ float g_as2[N_NODES];         // layer-2 alpha_src per node
__device__ float g_ad2[N_NODES];         // layer-2 alpha_dst per node
__device__ int   g_deg[N_NODES];         // in-degree histogram (zeroed by scan)
__device__ int   g_off[N_NODES + 1];     // CSR row offsets (by dst)
__device__ int   g_cur[N_NODES];         // scatter cursors
__device__ int   g_bsum[NSCAN];          // scan block sums
__device__ int   g_arrive;               // grid-barrier counters (self-reset)
__device__ int   g_depart;
__device__ int2  g_es[N_TOT];            // CSR payload: (src, adj bits)

// ---------------- fp16 mma helper ------------------------------------------
__device__ __forceinline__ void mma16n8k16_f16(float* d,
                                               uint32_t a0, uint32_t a1,
                                               uint32_t a2, uint32_t a3,
                                               uint32_t b0, uint32_t b1) {
    asm volatile(
        "mma.sync.aligned.m16n8k16.row.col.f32.f16.f16.f32 "
        "{%0,%1,%2,%3}, {%4,%5,%6,%7}, {%8,%9}, {%0,%1,%2,%3};"
        : "+f"(d[0]), "+f"(d[1]), "+f"(d[2]), "+f"(d[3])
        : "r"(a0), "r"(a1), "r"(a2), "r"(a3), "r"(b0), "r"(b1));
}

__device__ __forceinline__ uint2 split_pack(float v0, float v1) {
    __half h0 = __float2half_rn(v0), h1 = __float2half_rn(v1);
    __half l0 = __float2half_rn(v0 - __half2float(h0));
    __half l1 = __float2half_rn(v1 - __half2float(h1));
    __half2 hi2 = __halves2half2(h0, h1);
    __half2 lo2 = __halves2half2(l0, l1);
    return make_uint2(*(uint32_t*)&hi2, *(uint32_t*)&lo2);
}

// ---------------- K1: h1 = x @ W1 via 3x-FP16 (hi/lo) mma, fused alphas ----
#define B_STRIDE 68   // 64 + 4 uint2 pad -> conflict-free
__global__ __launch_bounds__(256, 2)
void gemm1_mma_kernel(const float* __restrict__ x,
                      const float* __restrict__ W1,
                      const float* __restrict__ a_src,
                      const float* __restrict__ a_dst) {
    extern __shared__ char smem_raw[];
    uint2* As = (uint2*)smem_raw;                    // [128][32] (hi2,lo2)
    uint2* Bs = (uint2*)(smem_raw + 128 * 32 * 8);   // [32][B_STRIDE]
    __shared__ float as_s[64], ad_s[64];

    const int t = threadIdx.x;
    const int rbase = blockIdx.x * 128;

    if (t < 64)       as_s[t]      = a_src[t];
    else if (t < 128) ad_s[t - 64] = a_dst[t - 64];

    const int w    = t >> 5;
    const int lane = t & 31;
    const int g    = lane >> 2;
    const int tg   = lane & 3;
    const int wr   = w * 16;

    float acc[8][4];
#pragma unroll
    for (int i = 0; i < 8; ++i)
#pragma unroll
        for (int j = 0; j < 4; ++j) acc[i][j] = 0.f;

    const int rowA  = wr + g;
    const int aSw   = (rowA & 3) << 2;

    for (int kc = 0; kc < 2; ++kc) {
        if (kc) __syncthreads();

#pragma unroll
        for (int i = 0; i < 16; ++i) {
            int fid = i * 256 + t;
            int row = fid >> 5, k2 = fid & 31;
            int gr  = rbase + row;
            float2 v = make_float2(0.f, 0.f);
            if (gr < N_NODES) v = *(const float2*)&x[gr * 128 + kc * 64 + k2 * 2];
            As[row * 32 + (k2 ^ ((row & 3) << 2))] = split_pack(v.x, v.y);
        }
#pragma unroll
        for (int i = 0; i < 8; ++i) {
            int fid = i * 256 + t;
            int k2 = fid >> 6, n = fid & 63;
            float v0 = W1[(kc * 64 + k2 * 2)     * 64 + n];
            float v1 = W1[(kc * 64 + k2 * 2 + 1) * 64 + n];
            Bs[k2 * B_STRIDE + n] = split_pack(v0, v1);
        }
        __syncthreads();

#pragma unroll
        for (int step = 0; step < 4; ++step) {
            const int k2a = step * 8 + tg;
            uint2 A0 = As[rowA * 32       + (k2a ^ aSw)];
            uint2 A1 = As[(rowA + 8) * 32 + (k2a ^ aSw)];
            uint2 A2 = As[rowA * 32       + ((k2a + 4) ^ aSw)];
            uint2 A3 = As[(rowA + 8) * 32 + ((k2a + 4) ^ aSw)];
            const int bRow0 = k2a * B_STRIDE + g;
            const int bRow1 = (k2a + 4) * B_STRIDE + g;
#pragma unroll
            for (int nt = 0; nt < 8; ++nt) {
                uint2 B0 = Bs[bRow0 + nt * 8];
                uint2 B1 = Bs[bRow1 + nt * 8];
                mma16n8k16_f16(acc[nt], A0.x, A1.x, A2.x, A3.x, B0.x, B1.x);
                mma16n8k16_f16(acc[nt], A0.y, A1.y, A2.y, A3.y, B0.x, B1.x);
                mma16n8k16_f16(acc[nt], A0.x, A1.x, A2.x, A3.x, B0.y, B1.y);
            }
        }
    }

    const int r0 = rbase + wr + g;
    const int r1 = r0 + 8;
    float pas0 = 0.f, pad0 = 0.f, pas1 = 0.f, pad1 = 0.f;
#pragma unroll
    for (int nt = 0; nt < 8; ++nt) {
        int c = nt * 8 + 2 * tg;
        float2 av = *(const float2*)&as_s[c];
        float2 dv = *(const float2*)&ad_s[c];
        pas0 += acc[nt][0] * av.x + acc[nt][1] * av.y;
        pad0 += acc[nt][0] * dv.x + acc[nt][1] * dv.y;
        pas1 += acc[nt][2] * av.x + acc[nt][3] * av.y;
        pad1 += acc[nt][2] * dv.x + acc[nt][3] * dv.y;
        if (r0 < N_NODES)
            g_h1h[r0 * 32 + nt * 4 + tg] = __floats2half2_rn(acc[nt][0], acc[nt][1]);
        if (r1 < N_NODES)
            g_h1h[r1 * 32 + nt * 4 + tg] = __floats2half2_rn(acc[nt][2], acc[nt][3]);
    }
#pragma unroll
    for (int off = 1; off <= 2; off <<= 1) {
        pas0 += __shfl_xor_sync(0xffffffffu, pas0, off);
        pad0 += __shfl_xor_sync(0xffffffffu, pad0, off);
        pas1 += __shfl_xor_sync(0xffffffffu, pas1, off);
        pad1 += __shfl_xor_sync(0xffffffffu, pad1, off);
    }
    if (tg == 0) {
        if (r0 < N_NODES) { g_as[r0] = pas0; g_ad[r0] = pad0; }
        if (r1 < N_NODES) { g_as[r1] = pas1; g_ad[r1] = pad1; }
    }
}

// ---------------- CSR build (side stream, overlapped with gemm1) -----------
__global__ void hist_kernel(const int* __restrict__ ei) {
    int t = blockIdx.x * blockDim.x + threadIdx.x;
    int e4 = t * 4;
    if (e4 + 3 < N_EDGES) {
        int4 d4 = *(const int4*)&ei[N_EDGES + e4];
        atomicAdd(&g_deg[d4.x], 1);
        atomicAdd(&g_deg[d4.y], 1);
        atomicAdd(&g_deg[d4.z], 1);
        atomicAdd(&g_deg[d4.w], 1);
    } else {
        for (int e = e4; e < N_EDGES && e < e4 + 4; ++e)
            atomicAdd(&g_deg[ei[N_EDGES + e]], 1);
    }
    if (t < N_NODES) atomicAdd(&g_deg[t], 1);
}

__global__ void fused_scan_kernel() {
    __shared__ int sh[256];
    __shared__ int bs[NSCAN];
    const int tid = threadIdx.x;
    const int b   = blockIdx.x;
    const int base = b * SCAN_B + tid * 4;

    int v[4];
#pragma unroll
    for (int k = 0; k < 4; ++k)
        v[k] = (base + k < N_NODES) ? g_deg[base + k] : 0;
    int local = v[0] + v[1] + v[2] + v[3];
    sh[tid] = local;
    __syncthreads();
    for (int off = 1; off < 256; off <<= 1) {
        int t2 = (tid >= off) ? sh[tid - off] : 0;
        __syncthreads();
        sh[tid] += t2;
        __syncthreads();
    }
    int incl = sh[tid];

    if (tid == 0) {
        g_bsum[b] = sh[255];
        __threadfence();
        atomicAdd(&g_arrive, 1);
        while (*(volatile int*)&g_arrive < NSCAN) { }
    }
    __syncthreads();

    if (tid < NSCAN) bs[tid] = *(volatile int*)&g_bsum[tid];
    __syncthreads();
    int bpre = 0;
    for (int i = 0; i < b; ++i) bpre += bs[i];

    int run = bpre + incl - local;
#pragma unroll
    for (int k = 0; k < 4; ++k) {
        if (base + k < N_NODES) {
            g_off[base + k] = run;
            g_cur[base + k] = run;
            g_deg[base + k] = 0;
        }
        run += v[k];
    }
    if (b == NSCAN - 1 && tid == 255) g_off[N_NODES] = N_TOT;

    __syncthreads();
    if (tid == 0) {
        int old = atomicAdd(&g_depart, 1);
        if (old == NSCAN - 1) { g_depart = 0; g_arrive = 0; }
    }
}

__global__ void scatter_kernel(const int* __restrict__ ei,
                               const float* __restrict__ ew) {
    int e = blockIdx.x * blockDim.x + threadIdx.x;
    if (e >= N_TOT) return;
    int s, d; float adj;
    if (e < N_EDGES) {
        s = ei[e]; d = ei[N_EDGES + e];
        adj = 1.f - 1.f / ew[e];
    } else {
        s = d = e - N_EDGES;
        adj = 0.f;
    }
    int pos = atomicAdd(&g_cur[d], 1);
    g_es[pos] = make_int2(s, __float_as_int(adj));
}

// ---------------- K2: fused layer-1 softmax+aggregate + layer-2 features ----
// 4 dst nodes per warp, 8 lanes per node; 4-edge batches for MLP.
__global__ void agg1_csr_kernel(const float* __restrict__ b1,
                                const float* __restrict__ W2,
                                const float* __restrict__ a_src2,
                                const float* __restrict__ a_dst2) {
    __shared__ float w2s[448];
    __shared__ float as2s[8], ad2s[8];
    __shared__ float b1s[64];
    int tid = threadIdx.x;
    if (tid < 224) { w2s[tid] = W2[tid]; w2s[tid + 224] = W2[tid + 224]; }
    if (tid < 7)   { as2s[tid] = a_src2[tid]; ad2s[tid] = a_dst2[tid]; }
    if (tid < 64)  b1s[tid] = b1[tid];
    __syncthreads();

    const int w    = tid >> 5;
    const int lane = tid & 31;
    const int sl   = lane & 7;
    const int d    = blockIdx.x * 32 + w * 4 + (lane >> 3);

    const float ad_d = g_ad[d];
    int j = g_off[d];
    const int end = g_off[d + 1];
    float den = 0.f;
    float acc[8];
#pragma unroll
    for (int k = 0; k < 8; ++k) acc[k] = 0.f;
    const uint4* h1p = (const uint4*)g_h1h;

    for (; j + 3 < end; j += 4) {
        int2 e[4];
#pragma unroll
        for (int q = 0; q < 4; ++q) e[q] = g_es[j + q];
        float sa[4]; uint4 hv[4];
#pragma unroll
        for (int q = 0; q < 4; ++q) {
            sa[q] = g_as[e[q].x];
            hv[q] = h1p[e[q].x * 8 + sl];
        }
#pragma unroll
        for (int q = 0; q < 4; ++q) {
            float xx = sa[q] + ad_d; xx = (xx > 0.f) ? xx : NEG_SLOPE * xx;
            float ea = __expf(xx + __int_as_float(e[q].y));
            den += ea;
            float2 f;
            f = __half22float2(*(__half2*)&hv[q].x); acc[0] += ea * f.x; acc[1] += ea * f.y;
            f = __half22float2(*(__half2*)&hv[q].y); acc[2] += ea * f.x; acc[3] += ea * f.y;
            f = __half22float2(*(__half2*)&hv[q].z); acc[4] += ea * f.x; acc[5] += ea * f.y;
            f = __half22float2(*(__half2*)&hv[q].w); acc[6] += ea * f.x; acc[7] += ea * f.y;
        }
    }
    if (j + 1 < end) {
        int2 e0 = g_es[j], e1 = g_es[j + 1];
        float sa0 = g_as[e0.x], sa1 = g_as[e1.x];
        uint4 hv0 = h1p[e0.x * 8 + sl];
        uint4 hv1 = h1p[e1.x * 8 + sl];
        float x0 = sa0 + ad_d; x0 = (x0 > 0.f) ? x0 : NEG_SLOPE * x0;
        float x1 = sa1 + ad_d; x1 = (x1 > 0.f) ? x1 : NEG_SLOPE * x1;
        float ea0 = __expf(x0 + __int_as_float(e0.y));
        float ea1 = __expf(x1 + __int_as_float(e1.y));
        den += ea0 + ea1;
        float2 f;
        f = __half22float2(*(__half2*)&hv0.x); acc[0] += ea0 * f.x; acc[1] += ea0 * f.y;
        f = __half22float2(*(__half2*)&hv0.y); acc[2] += ea0 * f.x; acc[3] += ea0 * f.y;
        f = __half22float2(*(__half2*)&hv0.z); acc[4] += ea0 * f.x; acc[5] += ea0 * f.y;
        f = __half22float2(*(__half2*)&hv0.w); acc[6] += ea0 * f.x; acc[7] += ea0 * f.y;
        f = __half22float2(*(__half2*)&hv1.x); acc[0] += ea1 * f.x; acc[1] += ea1 * f.y;
        f = __half22float2(*(__half2*)&hv1.y); acc[2] += ea1 * f.x; acc[3] += ea1 * f.y;
        f = __half22float2(*(__half2*)&hv1.z); acc[4] += ea1 * f.x; acc[5] += ea1 * f.y;
        f = __half22float2(*(__half2*)&hv1.w); acc[6] += ea1 * f.x; acc[7] += ea1 * f.y;
        j += 2;
    }
    if (j < end) {
        int2 e0 = g_es[j];
        float sa0 = g_as[e0.x];
        uint4 hv0 = h1p[e0.x * 8 + sl];
        float x0 = sa0 + ad_d; x0 = (x0 > 0.f) ? x0 : NEG_SLOPE * x0;
        float ea0 = __expf(x0 + __int_as_float(e0.y));
        den += ea0;
        float2 f;
        f = __half22float2(*(__half2*)&hv0.x); acc[0] += ea0 * f.x; acc[1] += ea0 * f.y;
        f = __half22float2(*(__half2*)&hv0.y); acc[2] += ea0 * f.x; acc[3] += ea0 * f.y;
        f = __half22float2(*(__half2*)&hv0.z); acc[4] += ea0 * f.x; acc[5] += ea0 * f.y;
        f = __half22float2(*(__half2*)&hv0.w); acc[6] += ea0 * f.x; acc[7] += ea0 * f.y;
    }

    const float inv = 1.f / (den + EPS);
    float p[7];
#pragma unroll
    for (int c = 0; c < 7; ++c) p[c] = 0.f;
#pragma unroll
    for (int k = 0; k < 8; ++k) {
        float fv = fmaxf(fmaf(acc[k], inv, b1s[sl * 8 + k]), 0.f);
        const float* wrow = &w2s[(sl * 8 + k) * 7];
#pragma unroll
        for (int c = 0; c < 7; ++c) p[c] += fv * wrow[c];
    }
#pragma unroll
    for (int off = 1; off <= 4; off <<= 1)
#pragma unroll
        for (int c = 0; c < 7; ++c)
            p[c] += __shfl_xor_sync(0xffffffffu, p[c], off);

    if (sl == 0) {
        float4 v0 = make_float4(p[0], p[1], p[2], p[3]);
        float4 v1 = make_float4(p[4], p[5], p[6], 0.f);
        *(float4*)&g_h2[d * 8]     = v0;
        *(float4*)&g_h2[d * 8 + 4] = v1;
        float s2 = 0.f, t2 = 0.f;
#pragma unroll
        for (int c = 0; c < 7; ++c) {
            s2 += p[c] * as2s[c];
            t2 += p[c] * ad2s[c];
        }
        g_as2[d] = s2;
        g_ad2[d] = t2;
    }
}

// ---------------- K3: fused layer-2 softmax+aggregate (8 lanes / dst) -------
// 8-edge batches for MLP.
__global__ void agg2_csr_kernel(float* __restrict__ out,
                                const float* __restrict__ b2) {
    int gt = blockIdx.x * blockDim.x + threadIdx.x;
    int d  = gt >> 3;
    int c  = gt & 7;
    if (d >= N_NODES) return;

    float ad_d = g_ad2[d];
    int j = g_off[d], end = g_off[d + 1];
    float den = 0.f, acc = 0.f;
    for (; j + 7 < end; j += 8) {
        int2 e[8];
#pragma unroll
        for (int q = 0; q < 8; ++q) e[q] = g_es[j + q];
        float sa[8], hv[8];
#pragma unroll
        for (int q = 0; q < 8; ++q) {
            sa[q] = g_as2[e[q].x];
            hv[q] = g_h2[e[q].x * 8 + c];
        }
#pragma unroll
        for (int q = 0; q < 8; ++q) {
            float a = sa[q] + ad_d; a = (a > 0.f) ? a : NEG_SLOPE * a;
            float ea = __expf(a + __int_as_float(e[q].y));
            den += ea; acc += ea * hv[q];
        }
    }
    if (j + 3 < end) {
        int2 e[4];
#pragma unroll
        for (int q = 0; q < 4; ++q) e[q] = g_es[j + q];
        float sa[4], hv[4];
#pragma unroll
        for (int q = 0; q < 4; ++q) {
            sa[q] = g_as2[e[q].x];
            hv[q] = g_h2[e[q].x * 8 + c];
        }
#pragma unroll
        for (int q = 0; q < 4; ++q) {
            float a = sa[q] + ad_d; a = (a > 0.f) ? a : NEG_SLOPE * a;
            float ea = __expf(a + __int_as_float(e[q].y));
            den += ea; acc += ea * hv[q];
        }
        j += 4;
    }
    for (; j < end; ++j) {
        int2 e0 = g_es[j];
        float a = g_as2[e0.x] + ad_d; a = (a > 0.f) ? a : NEG_SLOPE * a;
        float ea = __expf(a + __int_as_float(e0.y));
        den += ea;
        acc += ea * g_h2[e0.x * 8 + c];
    }
    if (c < 7)
        out[d * 7 + c] = fmaf(acc, 1.f / (den + EPS), b2[c]);
}

// ---------------- launch (fork-join: CSR build overlaps gemm1) -------------
extern "C" void kernel_launch(void* const* d_in, const int* in_sizes, int n_in,
                              void* d_out, int out_size) {
    const float* x      = (const float*)d_in[0];
    const int*   ei     = (const int*)  d_in[1];
    const float* ew     = (const float*)d_in[2];
    const float* W1     = (const float*)d_in[3];
    const float* a_src1 = (const float*)d_in[4];
    const float* a_dst1 = (const float*)d_in[5];
    const float* b1     = (const float*)d_in[6];
    const float* W2     = (const float*)d_in[7];
    const float* a_src2 = (const float*)d_in[8];
    const float* a_dst2 = (const float*)d_in[9];
    const float* b2     = (const float*)d_in[10];
    float* out = (float*)d_out;

    const int GEMM_SMEM = 128 * 32 * 8 + 32 * B_STRIDE * 8;   // ~50 KB

    static cudaStream_t s_side = nullptr;
    static cudaEvent_t ev_fork = nullptr, ev_join = nullptr;
    if (!s_side) {
        cudaStreamCreateWithFlags(&s_side, cudaStreamNonBlocking);
        cudaEventCreateWithFlags(&ev_fork, cudaEventDisableTiming);
        cudaEventCreateWithFlags(&ev_join, cudaEventDisableTiming);
        cudaFuncSetAttribute(gemm1_mma_kernel,
                             cudaFuncAttributeMaxDynamicSharedMemorySize,
                             GEMM_SMEM);
    }

    // fork: CSR build chain on side stream (hist -> scan -> scatter)
    cudaEventRecord(ev_fork, 0);
    cudaStreamWaitEvent(s_side, ev_fork, 0);
    hist_kernel<<<((N_EDGES + 3) / 4 + 255) / 256, 256, 0, s_side>>>(ei);
    fused_scan_kernel<<<NSCAN, 256, 0, s_side>>>();
    scatter_kernel<<<(N_TOT + 255) / 256, 256, 0, s_side>>>(ei, ew);
    cudaEventRecord(ev_join, s_side);

    // main stream: GEMM1 via 3x-FP16 mma (independent of CSR build)
    gemm1_mma_kernel<<<(N_NODES + 127) / 128, 256, GEMM_SMEM>>>(
        x, W1, a_src1, a_dst1);

    // join, then fused aggregations
    cudaStreamWaitEvent(0, ev_join, 0);
    agg1_csr_kernel<<<N_NODES / 32, 256>>>(b1, W2, a_src2, a_dst2);
    agg2_csr_kernel<<<(N_NODES * 8 + 255) / 256, 256>>>(out, b2);
}

// round 13
// speedup vs baseline: 1.4399x; 1.0130x over previous
#include <cuda_runtime.h>
#include <cuda_fp16.h>
#include <cstdint>

#define N_NODES 100000
#define N_EDGES 1600000
#define N_TOT   1700000           // edges + self loops
#define NEG_SLOPE 0.2f
#define EPS 1e-16f
#define SCAN_B 1024
#define NSCAN ((N_NODES + SCAN_B - 1) / SCAN_B)   // 98

// ---------------- scratch (device globals; no allocation allowed) ----------
__device__ __half2 g_h1h[N_NODES * 32];  // layer-1 features (fp16, gather-only)
__device__ float g_h2[N_NODES * 8];      // layer-2 features (padded 7->8)
__device__ float g_as[N_NODES];          // layer-1 alpha_src per node
__device__ float g_ad[N_NODES];          // layer-1 alpha_dst per node
__device__ float g_as2[N_NODES];         // layer-2 alpha_src per node
__device__ float g_ad2[N_NODES];         // layer-2 alpha_dst per node
__device__ int   g_deg[N_NODES];         // in-degree histogram (zeroed by scan)
__device__ int   g_off[N_NODES + 1];     // CSR row offsets (by dst)
__device__ int   g_cur[N_NODES];         // scatter cursors
__device__ int   g_bsum[NSCAN];          // scan block sums
__device__ int   g_arrive;               // grid-barrier counters (self-reset)
__device__ int   g_depart;
__device__ int2  g_es[N_TOT];            // CSR payload: (src, adj bits)

// ---------------- fp16 mma helper ------------------------------------------
__device__ __forceinline__ void mma16n8k16_f16(float* d,
                                               uint32_t a0, uint32_t a1,
                                               uint32_t a2, uint32_t a3,
                                               uint32_t b0, uint32_t b1) {
    asm volatile(
        "mma.sync.aligned.m16n8k16.row.col.f32.f16.f16.f32 "
        "{%0,%1,%2,%3}, {%4,%5,%6,%7}, {%8,%9}, {%0,%1,%2,%3};"
        : "+f"(d[0]), "+f"(d[1]), "+f"(d[2]), "+f"(d[3])
        : "r"(a0), "r"(a1), "r"(a2), "r"(a3), "r"(b0), "r"(b1));
}

__device__ __forceinline__ uint2 split_pack(float v0, float v1) {
    __half h0 = __float2half_rn(v0), h1 = __float2half_rn(v1);
    __half l0 = __float2half_rn(v0 - __half2float(h0));
    __half l1 = __float2half_rn(v1 - __half2float(h1));
    __half2 hi2 = __halves2half2(h0, h1);
    __half2 lo2 = __halves2half2(l0, l1);
    return make_uint2(*(uint32_t*)&hi2, *(uint32_t*)&lo2);
}

// ---------------- K1: h1 = x @ W1 via 3x-FP16 (hi/lo) mma, fused alphas ----
#define B_STRIDE 68   // 64 + 4 uint2 pad -> conflict-free
__global__ __launch_bounds__(256, 2)
void gemm1_mma_kernel(const float* __restrict__ x,
                      const float* __restrict__ W1,
                      const float* __restrict__ a_src,
                      const float* __restrict__ a_dst) {
    extern __shared__ char smem_raw[];
    uint2* As = (uint2*)smem_raw;                    // [128][32] (hi2,lo2)
    uint2* Bs = (uint2*)(smem_raw + 128 * 32 * 8);   // [32][B_STRIDE]
    __shared__ float as_s[64], ad_s[64];

    const int t = threadIdx.x;
    const int rbase = blockIdx.x * 128;

    if (t < 64)       as_s[t]      = a_src[t];
    else if (t < 128) ad_s[t - 64] = a_dst[t - 64];

    const int w    = t >> 5;
    const int lane = t & 31;
    const int g    = lane >> 2;
    const int tg   = lane & 3;
    const int wr   = w * 16;

    float acc[8][4];
#pragma unroll
    for (int i = 0; i < 8; ++i)
#pragma unroll
        for (int j = 0; j < 4; ++j) acc[i][j] = 0.f;

    const int rowA  = wr + g;
    const int aSw   = (rowA & 3) << 2;

    for (int kc = 0; kc < 2; ++kc) {
        if (kc) __syncthreads();

#pragma unroll
        for (int i = 0; i < 16; ++i) {
            int fid = i * 256 + t;
            int row = fid >> 5, k2 = fid & 31;
            int gr  = rbase + row;
            float2 v = make_float2(0.f, 0.f);
            if (gr < N_NODES) v = *(const float2*)&x[gr * 128 + kc * 64 + k2 * 2];
            As[row * 32 + (k2 ^ ((row & 3) << 2))] = split_pack(v.x, v.y);
        }
#pragma unroll
        for (int i = 0; i < 8; ++i) {
            int fid = i * 256 + t;
            int k2 = fid >> 6, n = fid & 63;
            float v0 = W1[(kc * 64 + k2 * 2)     * 64 + n];
            float v1 = W1[(kc * 64 + k2 * 2 + 1) * 64 + n];
            Bs[k2 * B_STRIDE + n] = split_pack(v0, v1);
        }
        __syncthreads();

#pragma unroll
        for (int step = 0; step < 4; ++step) {
            const int k2a = step * 8 + tg;
            uint2 A0 = As[rowA * 32       + (k2a ^ aSw)];
            uint2 A1 = As[(rowA + 8) * 32 + (k2a ^ aSw)];
            uint2 A2 = As[rowA * 32       + ((k2a + 4) ^ aSw)];
            uint2 A3 = As[(rowA + 8) * 32 + ((k2a + 4) ^ aSw)];
            const int bRow0 = k2a * B_STRIDE + g;
            const int bRow1 = (k2a + 4) * B_STRIDE + g;
#pragma unroll
            for (int nt = 0; nt < 8; ++nt) {
                uint2 B0 = Bs[bRow0 + nt * 8];
                uint2 B1 = Bs[bRow1 + nt * 8];
                mma16n8k16_f16(acc[nt], A0.x, A1.x, A2.x, A3.x, B0.x, B1.x);
                mma16n8k16_f16(acc[nt], A0.y, A1.y, A2.y, A3.y, B0.x, B1.x);
                mma16n8k16_f16(acc[nt], A0.x, A1.x, A2.x, A3.x, B0.y, B1.y);
            }
        }
    }

    const int r0 = rbase + wr + g;
    const int r1 = r0 + 8;
    float pas0 = 0.f, pad0 = 0.f, pas1 = 0.f, pad1 = 0.f;
#pragma unroll
    for (int nt = 0; nt < 8; ++nt) {
        int c = nt * 8 + 2 * tg;
        float2 av = *(const float2*)&as_s[c];
        float2 dv = *(const float2*)&ad_s[c];
        pas0 += acc[nt][0] * av.x + acc[nt][1] * av.y;
        pad0 += acc[nt][0] * dv.x + acc[nt][1] * dv.y;
        pas1 += acc[nt][2] * av.x + acc[nt][3] * av.y;
        pad1 += acc[nt][2] * dv.x + acc[nt][3] * dv.y;
        if (r0 < N_NODES)
            g_h1h[r0 * 32 + nt * 4 + tg] = __floats2half2_rn(acc[nt][0], acc[nt][1]);
        if (r1 < N_NODES)
            g_h1h[r1 * 32 + nt * 4 + tg] = __floats2half2_rn(acc[nt][2], acc[nt][3]);
    }
#pragma unroll
    for (int off = 1; off <= 2; off <<= 1) {
        pas0 += __shfl_xor_sync(0xffffffffu, pas0, off);
        pad0 += __shfl_xor_sync(0xffffffffu, pad0, off);
        pas1 += __shfl_xor_sync(0xffffffffu, pas1, off);
        pad1 += __shfl_xor_sync(0xffffffffu, pad1, off);
    }
    if (tg == 0) {
        if (r0 < N_NODES) { g_as[r0] = pas0; g_ad[r0] = pad0; }
        if (r1 < N_NODES) { g_as[r1] = pas1; g_ad[r1] = pad1; }
    }
}

// ---------------- CSR build (side stream, overlapped with gemm1) -----------
__global__ void hist_kernel(const int* __restrict__ ei) {
    int t = blockIdx.x * blockDim.x + threadIdx.x;
    int e4 = t * 4;
    if (e4 + 3 < N_EDGES) {
        int4 d4 = *(const int4*)&ei[N_EDGES + e4];
        atomicAdd(&g_deg[d4.x], 1);
        atomicAdd(&g_deg[d4.y], 1);
        atomicAdd(&g_deg[d4.z], 1);
        atomicAdd(&g_deg[d4.w], 1);
    } else {
        for (int e = e4; e < N_EDGES && e < e4 + 4; ++e)
            atomicAdd(&g_deg[ei[N_EDGES + e]], 1);
    }
    if (t < N_NODES) atomicAdd(&g_deg[t], 1);
}

__global__ void fused_scan_kernel() {
    __shared__ int sh[256];
    __shared__ int bs[NSCAN];
    const int tid = threadIdx.x;
    const int b   = blockIdx.x;
    const int base = b * SCAN_B + tid * 4;

    int v[4];
#pragma unroll
    for (int k = 0; k < 4; ++k)
        v[k] = (base + k < N_NODES) ? g_deg[base + k] : 0;
    int local = v[0] + v[1] + v[2] + v[3];
    sh[tid] = local;
    __syncthreads();
    for (int off = 1; off < 256; off <<= 1) {
        int t2 = (tid >= off) ? sh[tid - off] : 0;
        __syncthreads();
        sh[tid] += t2;
        __syncthreads();
    }
    int incl = sh[tid];

    if (tid == 0) {
        g_bsum[b] = sh[255];
        __threadfence();
        atomicAdd(&g_arrive, 1);
        while (*(volatile int*)&g_arrive < NSCAN) { }
    }
    __syncthreads();

    if (tid < NSCAN) bs[tid] = *(volatile int*)&g_bsum[tid];
    __syncthreads();
    int bpre = 0;
    for (int i = 0; i < b; ++i) bpre += bs[i];

    int run = bpre + incl - local;
#pragma unroll
    for (int k = 0; k < 4; ++k) {
        if (base + k < N_NODES) {
            g_off[base + k] = run;
            g_cur[base + k] = run;
            g_deg[base + k] = 0;
        }
        run += v[k];
    }
    if (b == NSCAN - 1 && tid == 255) g_off[N_NODES] = N_TOT;

    __syncthreads();
    if (tid == 0) {
        int old = atomicAdd(&g_depart, 1);
        if (old == NSCAN - 1) { g_depart = 0; g_arrive = 0; }
    }
}

__global__ void scatter_kernel(const int* __restrict__ ei,
                               const float* __restrict__ ew) {
    int e = blockIdx.x * blockDim.x + threadIdx.x;
    if (e >= N_TOT) return;
    int s, d; float adj;
    if (e < N_EDGES) {
        s = ei[e]; d = ei[N_EDGES + e];
        adj = 1.f - 1.f / ew[e];
    } else {
        s = d = e - N_EDGES;
        adj = 0.f;
    }
    int pos = atomicAdd(&g_cur[d], 1);
    g_es[pos] = make_int2(s, __float_as_int(adj));
}

// ---------------- K2: fused layer-1 softmax+aggregate + layer-2 features ----
// 4 dst nodes per warp, 8 lanes per node. Per 8-edge batch, each lane computes
// the exp for ONE edge and broadcasts (ea, src) via subgroup shuffles.
__global__ void agg1_csr_kernel(const float* __restrict__ b1,
                                const float* __restrict__ W2,
                                const float* __restrict__ a_src2,
                                const float* __restrict__ a_dst2) {
    __shared__ float w2s[448];
    __shared__ float as2s[8], ad2s[8];
    __shared__ float b1s[64];
    int tid = threadIdx.x;
    if (tid < 224) { w2s[tid] = W2[tid]; w2s[tid + 224] = W2[tid + 224]; }
    if (tid < 7)   { as2s[tid] = a_src2[tid]; ad2s[tid] = a_dst2[tid]; }
    if (tid < 64)  b1s[tid] = b1[tid];
    __syncthreads();

    const int w    = tid >> 5;
    const int lane = tid & 31;
    const int sl   = lane & 7;
    const unsigned sgmask = 0xFFu << (lane & 24);
    const int d    = blockIdx.x * 32 + w * 4 + (lane >> 3);

    const float ad_d = g_ad[d];
    const int beg = g_off[d], end = g_off[d + 1];
    float den = 0.f;
    float acc[8];
#pragma unroll
    for (int k = 0; k < 8; ++k) acc[k] = 0.f;
    const uint4* h1p = (const uint4*)g_h1h;

    for (int j = beg; j < end; j += 8) {
        int idx = j + sl;
        bool valid = idx < end;
        int2 e = g_es[valid ? idx : end - 1];   // deg>=1 (self loop)
        float sa = g_as[e.x];
        float xx = sa + ad_d; xx = (xx > 0.f) ? xx : NEG_SLOPE * xx;
        float ea = __expf(xx + __int_as_float(e.y));
        if (!valid) ea = 0.f;
#pragma unroll
        for (int q = 0; q < 8; ++q) {
            float eaq = __shfl_sync(sgmask, ea, q, 8);
            int   sxq = __shfl_sync(sgmask, e.x, q, 8);
            uint4 hv = h1p[sxq * 8 + sl];
            den += eaq;
            float2 f;
            f = __half22float2(*(__half2*)&hv.x); acc[0] += eaq * f.x; acc[1] += eaq * f.y;
            f = __half22float2(*(__half2*)&hv.y); acc[2] += eaq * f.x; acc[3] += eaq * f.y;
            f = __half22float2(*(__half2*)&hv.z); acc[4] += eaq * f.x; acc[5] += eaq * f.y;
            f = __half22float2(*(__half2*)&hv.w); acc[6] += eaq * f.x; acc[7] += eaq * f.y;
        }
    }

    const float inv = 1.f / (den + EPS);
    float p[7];
#pragma unroll
    for (int c = 0; c < 7; ++c) p[c] = 0.f;
#pragma unroll
    for (int k = 0; k < 8; ++k) {
        float fv = fmaxf(fmaf(acc[k], inv, b1s[sl * 8 + k]), 0.f);
        const float* wrow = &w2s[(sl * 8 + k) * 7];
#pragma unroll
        for (int c = 0; c < 7; ++c) p[c] += fv * wrow[c];
    }
#pragma unroll
    for (int off = 1; off <= 4; off <<= 1)
#pragma unroll
        for (int c = 0; c < 7; ++c)
            p[c] += __shfl_xor_sync(0xffffffffu, p[c], off);

    if (sl == 0) {
        float4 v0 = make_float4(p[0], p[1], p[2], p[3]);
        float4 v1 = make_float4(p[4], p[5], p[6], 0.f);
        *(float4*)&g_h2[d * 8]     = v0;
        *(float4*)&g_h2[d * 8 + 4] = v1;
        float s2 = 0.f, t2 = 0.f;
#pragma unroll
        for (int c = 0; c < 7; ++c) {
            s2 += p[c] * as2s[c];
            t2 += p[c] * ad2s[c];
        }
        g_as2[d] = s2;
        g_ad2[d] = t2;
    }
}

// ---------------- K3: fused layer-2 softmax+aggregate (8 lanes / dst) -------
// Same dedup-exp pattern: one exp per edge, shuffled to the subgroup.
__global__ void agg2_csr_kernel(float* __restrict__ out,
                                const float* __restrict__ b2) {
    int tid  = threadIdx.x;
    int lane = tid & 31;
    int c    = lane & 7;
    const unsigned sgmask = 0xFFu << (lane & 24);
    int d = (blockIdx.x * blockDim.x + tid) >> 3;
    if (d >= N_NODES) return;

    const float ad_d = g_ad2[d];
    const int beg = g_off[d], end = g_off[d + 1];
    float den = 0.f, acc = 0.f;

    for (int j = beg; j < end; j += 8) {
        int idx = j + c;
        bool valid = idx < end;
        int2 e = g_es[valid ? idx : end - 1];
        float sa = g_as2[e.x];
        float a = sa + ad_d; a = (a > 0.f) ? a : NEG_SLOPE * a;
        float ea = __expf(a + __int_as_float(e.y));
        if (!valid) ea = 0.f;
#pragma unroll
        for (int q = 0; q < 8; ++q) {
            float eaq = __shfl_sync(sgmask, ea, q, 8);
            int   sxq = __shfl_sync(sgmask, e.x, q, 8);
            float hv = g_h2[sxq * 8 + c];
            den += eaq;
            acc += eaq * hv;
        }
    }
    if (c < 7)
        out[d * 7 + c] = fmaf(acc, 1.f / (den + EPS), b2[c]);
}

// ---------------- launch (fork-join: CSR build overlaps gemm1) -------------
extern "C" void kernel_launch(void* const* d_in, const int* in_sizes, int n_in,
                              void* d_out, int out_size) {
    const float* x      = (const float*)d_in[0];
    const int*   ei     = (const int*)  d_in[1];
    const float* ew     = (const float*)d_in[2];
    const float* W1     = (const float*)d_in[3];
    const float* a_src1 = (const float*)d_in[4];
    const float* a_dst1 = (const float*)d_in[5];
    const float* b1     = (const float*)d_in[6];
    const float* W2     = (const float*)d_in[7];
    const float* a_src2 = (const float*)d_in[8];
    const float* a_dst2 = (const float*)d_in[9];
    const float* b2     = (const float*)d_in[10];
    float* out = (float*)d_out;

    const int GEMM_SMEM = 128 * 32 * 8 + 32 * B_STRIDE * 8;   // ~50 KB

    static cudaStream_t s_side = nullptr;
    static cudaEvent_t ev_fork = nullptr, ev_join = nullptr;
    if (!s_side) {
        cudaStreamCreateWithFlags(&s_side, cudaStreamNonBlocking);
        cudaEventCreateWithFlags(&ev_fork, cudaEventDisableTiming);
        cudaEventCreateWithFlags(&ev_join, cudaEventDisableTiming);
        cudaFuncSetAttribute(gemm1_mma_kernel,
                             cudaFuncAttributeMaxDynamicSharedMemorySize,
                             GEMM_SMEM);
    }

    // fork: CSR build chain on side stream (hist -> scan -> scatter)
    cudaEventRecord(ev_fork, 0);
    cudaStreamWaitEvent(s_side, ev_fork, 0);
    hist_kernel<<<((N_EDGES + 3) / 4 + 255) / 256, 256, 0, s_side>>>(ei);
    fused_scan_kernel<<<NSCAN, 256, 0, s_side>>>();
    scatter_kernel<<<(N_TOT + 255) / 256, 256, 0, s_side>>>(ei, ew);
    cudaEventRecord(ev_join, s_side);

    // main stream: GEMM1 via 3x-FP16 mma (independent of CSR build)
    gemm1_mma_kernel<<<(N_NODES + 127) / 128, 256, GEMM_SMEM>>>(
        x, W1, a_src1, a_dst1);

    // join, then fused aggregations
    cudaStreamWaitEvent(0, ev_join, 0);
    agg1_csr_kernel<<<N_NODES / 32, 256>>>(b1, W2, a_src2, a_dst2);
    agg2_csr_kernel<<<(N_NODES * 8 + 255) / 256, 256>>>(out, b2);
}